// round 14
// baseline (speedup 1.0000x reference)
#include <cuda_runtime.h>
#include <math.h>

// dims
#define E    256
#define H    128
#define NQ   8
#define QED  64
#define HYP  64
#define NA   14
#define BS   4096
#define BSG  512

// output layout: sorted_q [BS,NA,NQ] | h [BS,H] | rq [BSG,NQ]
#define OFF_SQ 0
#define OFF_H  (BS*NA*NQ)
#define OFF_RQ (OFF_H + BS*H)

// scratch weights (built cooperatively by k_main prologue)
__device__ __align__(16) float g_W[H*2*H];        // [128][256]
__device__ __align__(16) float g_wrz[2*H*2*H];    // [256][256]
__device__ __align__(16) float g_wn[H*2*H];       // [128][256]
__device__ unsigned long long g_ctr = 0ULL;       // monotonic epoch counter

typedef unsigned long long u64t;
__device__ __forceinline__ u64t pk2(float a) {
    u64t r; asm("mov.b64 %0, {%1,%1};" : "=l"(r) : "f"(a)); return r;
}
__device__ __forceinline__ u64t pk2b(float a, float b) {
    u64t r; asm("mov.b64 %0, {%1,%2};" : "=l"(r) : "f"(a), "f"(b)); return r;
}
__device__ __forceinline__ void fma2(u64t& d, u64t a, u64t b) {
    asm("fma.rn.f32x2 %0, %1, %2, %3;" : "=l"(d) : "l"(a), "l"(b), "l"(d));
}
__device__ __forceinline__ float2 upk(u64t v) {
    float2 f; asm("mov.b64 {%0,%1}, %2;" : "=f"(f.x), "=f"(f.y) : "l"(v)); return f;
}
__device__ __forceinline__ float sigm(float x) {
    return __fdividef(1.f, 1.f + __expf(-x));
}

// cp.async helpers
__device__ __forceinline__ void cpa16(unsigned s, const void* g) {
    asm volatile("cp.async.cg.shared.global [%0], [%1], 16;" :: "r"(s), "l"(g));
}
__device__ __forceinline__ void cpcommit() { asm volatile("cp.async.commit_group;"); }
__device__ __forceinline__ void cpwait0()  { asm volatile("cp.async.wait_group 0;"); }

// ---------------------------------------------------------------------------
// fused everything. 128 threads, 16 rows/block, 256 blocks, 3 CTAs/SM.
// rowA = lane&7 (rows rowA, rowA+8); c0 = (warp*4 + (lane>>3))*8.
// 40 weight tiles of 16KB, 2 buffers, 1 barrier per tile.
#define ROWS 16
#define SC_STR 260
#define SX_STR 132
#define SC_F (ROWS*SC_STR)
#define SX_F (ROWS*SX_STR)
#define SB_F (2*4096)
#define SMEM_BYTES ((SC_F + SX_F + SB_F)*4)

__device__ __forceinline__ void stage16k(unsigned sbu, int bufi,
                                         const float* src, int tid) {
    unsigned d = sbu + (unsigned)(bufi*16384 + tid*16);
    const char* s = (const char*)src + tid*16;
    #pragma unroll
    for (int i = 0; i < 8; i++) cpa16(d + i*2048, s + i*2048);
}

// dual-row, 128-wide step (fc1)
#define STEP128(KK, A0, A1) { \
    const float* wr_ = bw + (KK)*128 + c0; \
    ulonglong2 w01_ = *(const ulonglong2*)wr_; \
    ulonglong2 w23_ = *(const ulonglong2*)(wr_ + 4); \
    u64t a0_ = pk2(A0), a1_ = pk2(A1); \
    fma2(X0[0], a0_, w01_.x); fma2(X0[1], a0_, w01_.y); \
    fma2(X0[2], a0_, w23_.x); fma2(X0[3], a0_, w23_.y); \
    fma2(X1[0], a1_, w01_.x); fma2(X1[1], a1_, w01_.y); \
    fma2(X1[2], a1_, w23_.x); fma2(X1[3], a1_, w23_.y); }

// dual-row, 256-wide step (emb / gru-rz): halves use same activations
#define STEP256(AC0, AC1, BC0, BC1, KK, A0, A1) { \
    const float* wr_ = bw + (KK)*256 + c0; \
    ulonglong2 p01_ = *(const ulonglong2*)wr_; \
    ulonglong2 p23_ = *(const ulonglong2*)(wr_ + 4); \
    ulonglong2 q01_ = *(const ulonglong2*)(wr_ + 128); \
    ulonglong2 q23_ = *(const ulonglong2*)(wr_ + 132); \
    u64t a0_ = pk2(A0), a1_ = pk2(A1); \
    fma2(AC0[0], a0_, p01_.x); fma2(AC0[1], a0_, p01_.y); \
    fma2(AC0[2], a0_, p23_.x); fma2(AC0[3], a0_, p23_.y); \
    fma2(AC1[0], a1_, p01_.x); fma2(AC1[1], a1_, p01_.y); \
    fma2(AC1[2], a1_, p23_.x); fma2(AC1[3], a1_, p23_.y); \
    fma2(BC0[0], a0_, q01_.x); fma2(BC0[1], a0_, q01_.y); \
    fma2(BC0[2], a0_, q23_.x); fma2(BC0[3], a0_, q23_.y); \
    fma2(BC1[0], a1_, q01_.x); fma2(BC1[1], a1_, q01_.y); \
    fma2(BC1[2], a1_, q23_.x); fma2(BC1[3], a1_, q23_.y); }

// dual-row, 256-wide step (gru-n): p-half uses x2, q-half uses h
#define STEPN(KK, XA0, XA1, HA0, HA1) { \
    const float* wr_ = bw + (KK)*256 + c0; \
    ulonglong2 p01_ = *(const ulonglong2*)wr_; \
    ulonglong2 p23_ = *(const ulonglong2*)(wr_ + 4); \
    ulonglong2 q01_ = *(const ulonglong2*)(wr_ + 128); \
    ulonglong2 q23_ = *(const ulonglong2*)(wr_ + 132); \
    u64t x0_ = pk2(XA0), x1_ = pk2(XA1); \
    u64t h0_ = pk2(HA0), h1_ = pk2(HA1); \
    fma2(N0[0], x0_, p01_.x); fma2(N0[1], x0_, p01_.y); \
    fma2(N0[2], x0_, p23_.x); fma2(N0[3], x0_, p23_.y); \
    fma2(N1[0], x1_, p01_.x); fma2(N1[1], x1_, p01_.y); \
    fma2(N1[2], x1_, p23_.x); fma2(N1[3], x1_, p23_.y); \
    fma2(G0[0], h0_, q01_.x); fma2(G0[1], h0_, q01_.y); \
    fma2(G0[2], h0_, q23_.x); fma2(G0[3], h0_, q23_.y); \
    fma2(G1[0], h1_, q01_.x); fma2(G1[1], h1_, q01_.y); \
    fma2(G1[2], h1_, q23_.x); fma2(G1[3], h1_, q23_.y); }

__global__ __launch_bounds__(128, 3)
void k_main(const float* __restrict__ in, const float* __restrict__ hprev,
            const float* __restrict__ fc1_w, const float* __restrict__ fc1_b,
            const float* __restrict__ hyp_w1, const float* __restrict__ hyp_b1,
            const float* __restrict__ hyp_w2, const float* __restrict__ hyp_b2,
            const float* __restrict__ merger_w,
            const float* __restrict__ gwi,  const float* __restrict__ gwh,
            const float* __restrict__ gbi,  const float* __restrict__ gbh,
            const float* __restrict__ rq_in,
            const float* __restrict__ phi_w, const float* __restrict__ phi_b,
            const float* __restrict__ fc2_w, const float* __restrict__ fc2_b,
            float* __restrict__ out) {
    extern __shared__ float smem[];
    float* sC = smem;
    float* sX = smem + SC_F;
    float* sB = smem + SC_F + SX_F;
    unsigned sbu = (unsigned)__cvta_generic_to_shared(sB);

    const int tid  = threadIdx.x;
    const int lane = tid & 31;
    const int warp = tid >> 5;              // 0..3
    const int rowA = lane & 7;
    const int c0   = (warp*4 + (lane >> 3))*8;   // 0..120
    const int row0 = blockIdx.x * ROWS;

    // ======== distributed weight prep: 1/256 slice per CTA ========
    unsigned long long ticket = 0ULL;
    {
        float* sh = sX;   // 64 floats, consumed before sX reuse
        if (tid < HYP) {
            float s = hyp_b1[tid];
            #pragma unroll
            for (int q = 0; q < NQ; q++) s += hyp_w1[q*HYP + tid];
            sh[tid] = fmaxf(s, 0.f);
        }
        __syncthreads();
        {   // buildW: one output per thread
            int m = blockIdx.x*128 + tid;
            float acc = hyp_b2[m];
            #pragma unroll 16
            for (int f = 0; f < HYP; f++) acc = fmaf(sh[f], hyp_w2[f*32768 + m], acc);
            g_W[m] = acc;
        }
        #pragma unroll
        for (int s = 0; s < 2; s++) {       // wrz: 2 per thread
            int idx = blockIdx.x*256 + s*128 + tid;
            int k = idx >> 8, j = idx & 255;
            g_wrz[idx] = (k < 128) ? gwi[j*128 + k] : gwh[j*128 + (k - 128)];
        }
        {   // wn: 1 per thread
            int idx = blockIdx.x*128 + tid;
            int k = idx >> 8, j = idx & 255;
            g_wn[idx] = (j < 128) ? gwi[(256 + j)*128 + k] : gwh[(128 + j)*128 + k];
        }
        __threadfence();
        __syncthreads();
        if (tid == 0) ticket = atomicAdd(&g_ctr, 1ULL);
    }

    // prefetch fc1 tile 0 + stage input A [16][256] -> sC
    stage16k(sbu, 0, fc1_w, tid); cpcommit();
    {
        const float4* src = (const float4*)(in + row0*E);
        #pragma unroll
        for (int i = tid; i < 1024; i += 128) {
            float4 v = src[i];
            int f = i * 4;
            int r = f >> 8, cc = f & 255;
            float* p = sC + r*SC_STR + cc;
            p[0] = v.x; p[1] = v.y; p[2] = v.z; p[3] = v.w;
        }
    }

    // ======== FC1 : tiles g=0..7, KT=32, width 128 ========
    u64t X0[4], X1[4];
    {
        float4 b0 = *(const float4*)(fc1_b + c0);
        float4 b1 = *(const float4*)(fc1_b + c0 + 4);
        X0[0] = pk2b(b0.x, b0.y); X0[1] = pk2b(b0.z, b0.w);
        X0[2] = pk2b(b1.x, b1.y); X0[3] = pk2b(b1.z, b1.w);
        X1[0] = X0[0]; X1[1] = X0[1]; X1[2] = X0[2]; X1[3] = X0[3];
    }
    #pragma unroll 1
    for (int t = 0; t < 8; t++) {
        int g = t;
        cpwait0();
        __syncthreads();
        if (t == 7) {   // g_W about to be staged: wait for all CTAs' wprep
            if (tid == 0) {
                unsigned long long target = ((ticket >> 8) + 1) << 8;
                unsigned long long v;
                do {
                    asm volatile("ld.acquire.gpu.global.u64 %0, [%1];"
                                 : "=l"(v) : "l"(&g_ctr));
                } while (v < target);
            }
            __syncthreads();
        }
        const float* nsrc = (t < 7) ? (fc1_w + (t+1)*4096) : g_W;
        stage16k(sbu, (g+1)&1, nsrc, tid); cpcommit();
        const float* bw = sB + (g&1)*4096;
        const float4* a0v = (const float4*)(sC + rowA*SC_STR + t*32);
        const float4* a1v = a0v + (8*SC_STR)/4;
        #pragma unroll 4
        for (int k4 = 0; k4 < 8; k4++) {
            float4 a0q = a0v[k4];
            float4 a1q = a1v[k4];
            STEP128(k4*4+0, a0q.x, a1q.x);
            STEP128(k4*4+1, a0q.y, a1q.y);
            STEP128(k4*4+2, a0q.z, a1q.z);
            STEP128(k4*4+3, a0q.w, a1q.w);
        }
    }
    {
        float* xo0 = sX + rowA*SX_STR + c0;
        float* xo1 = xo0 + 8*SX_STR;
        #pragma unroll
        for (int cc = 0; cc < 4; cc++) {
            float2 v0 = upk(X0[cc]);
            float2 v1 = upk(X1[cc]);
            xo0[2*cc]   = fmaxf(v0.x, 0.f); xo0[2*cc+1] = fmaxf(v0.y, 0.f);
            xo1[2*cc]   = fmaxf(v1.x, 0.f); xo1[2*cc+1] = fmaxf(v1.y, 0.f);
        }
    }

    // ======== EMB : tiles g=8..15, KT=16, width 256 ========
    u64t P0[4] = {0,0,0,0}, P1[4] = {0,0,0,0};
    u64t Q0[4] = {0,0,0,0}, Q1[4] = {0,0,0,0};
    #pragma unroll 1
    for (int t = 0; t < 8; t++) {
        int g = 8 + t;
        cpwait0();
        __syncthreads();
        const float* nsrc = (t < 7) ? (g_W + (t+1)*4096) : g_wrz;
        stage16k(sbu, (g+1)&1, nsrc, tid); cpcommit();
        const float* bw = sB + (g&1)*4096;
        const float4* a0v = (const float4*)(sX + rowA*SX_STR + t*16);
        const float4* a1v = a0v + (8*SX_STR)/4;
        #pragma unroll
        for (int k4 = 0; k4 < 4; k4++) {
            float4 a0q = a0v[k4];
            float4 a1q = a1v[k4];
            STEP256(P0, P1, Q0, Q1, k4*4+0, a0q.x, a1q.x);
            STEP256(P0, P1, Q0, Q1, k4*4+1, a0q.y, a1q.y);
            STEP256(P0, P1, Q0, Q1, k4*4+2, a0q.z, a1q.z);
            STEP256(P0, P1, Q0, Q1, k4*4+3, a0q.w, a1q.w);
        }
    }

    // ---- merge (inline msm) + relu -> x2 into sC[0,128); stage hprev -> sC[128,256)
    {
        float m0v[8], m1v[8];
        #pragma unroll
        for (int cc = 0; cc < 8; cc++) {
            float a = merger_w[c0 + cc], b = merger_w[H + c0 + cc];
            float m = fmaxf(a, b);
            float e0 = expf(a - m), e1 = expf(b - m);
            float inv = 1.f / (e0 + e1);
            m0v[cc] = e0 * inv;
            m1v[cc] = e1 * inv;
        }
        float* co0 = sC + rowA*SC_STR + c0;
        float* co1 = co0 + 8*SC_STR;
        #pragma unroll
        for (int cc = 0; cc < 4; cc++) {
            float2 a0 = upk(P0[cc]); float2 b0 = upk(Q0[cc]);
            float2 a1 = upk(P1[cc]); float2 b1 = upk(Q1[cc]);
            co0[2*cc]   = fmaxf(fmaf(m0v[2*cc],   a0.x, m1v[2*cc]  *b0.x), 0.f);
            co0[2*cc+1] = fmaxf(fmaf(m0v[2*cc+1], a0.y, m1v[2*cc+1]*b0.y), 0.f);
            co1[2*cc]   = fmaxf(fmaf(m0v[2*cc],   a1.x, m1v[2*cc]  *b1.x), 0.f);
            co1[2*cc+1] = fmaxf(fmaf(m0v[2*cc+1], a1.y, m1v[2*cc+1]*b1.y), 0.f);
        }
        const float4* hsrc = (const float4*)(hprev + row0*H);
        #pragma unroll
        for (int i = tid; i < 512; i += 128) {
            float4 v = hsrc[i];
            int f = i * 4;
            int r = f >> 7, cc = f & 127;
            float* p = sC + r*SC_STR + 128 + cc;
            p[0] = v.x; p[1] = v.y; p[2] = v.z; p[3] = v.w;
        }
    }

    // ======== GRU r,z : tiles g=16..31, KT=16, width 256 ========
    float rs[2][8], zs[2][8];
    {
        u64t R0[4], R1[4], Z0[4], Z1[4];
        {
            float4 bi0 = *(const float4*)(gbi + c0);
            float4 bi1 = *(const float4*)(gbi + c0 + 4);
            float4 bh0 = *(const float4*)(gbh + c0);
            float4 bh1 = *(const float4*)(gbh + c0 + 4);
            R0[0] = pk2b(bi0.x+bh0.x, bi0.y+bh0.y);
            R0[1] = pk2b(bi0.z+bh0.z, bi0.w+bh0.w);
            R0[2] = pk2b(bi1.x+bh1.x, bi1.y+bh1.y);
            R0[3] = pk2b(bi1.z+bh1.z, bi1.w+bh1.w);
            float4 ci0 = *(const float4*)(gbi + H + c0);
            float4 ci1 = *(const float4*)(gbi + H + c0 + 4);
            float4 ch0 = *(const float4*)(gbh + H + c0);
            float4 ch1 = *(const float4*)(gbh + H + c0 + 4);
            Z0[0] = pk2b(ci0.x+ch0.x, ci0.y+ch0.y);
            Z0[1] = pk2b(ci0.z+ch0.z, ci0.w+ch0.w);
            Z0[2] = pk2b(ci1.x+ch1.x, ci1.y+ch1.y);
            Z0[3] = pk2b(ci1.z+ch1.z, ci1.w+ch1.w);
            #pragma unroll
            for (int i = 0; i < 4; i++) { R1[i] = R0[i]; Z1[i] = Z0[i]; }
        }
        #pragma unroll 1
        for (int t = 0; t < 16; t++) {
            int g = 16 + t;
            cpwait0();
            __syncthreads();
            const float* nsrc = (t < 15) ? (g_wrz + (t+1)*4096) : g_wn;
            stage16k(sbu, (g+1)&1, nsrc, tid); cpcommit();
            const float* bw = sB + (g&1)*4096;
            const float4* a0v = (const float4*)(sC + rowA*SC_STR + t*16);
            const float4* a1v = a0v + (8*SC_STR)/4;
            #pragma unroll
            for (int k4 = 0; k4 < 4; k4++) {
                float4 a0q = a0v[k4];
                float4 a1q = a1v[k4];
                STEP256(R0, R1, Z0, Z1, k4*4+0, a0q.x, a1q.x);
                STEP256(R0, R1, Z0, Z1, k4*4+1, a0q.y, a1q.y);
                STEP256(R0, R1, Z0, Z1, k4*4+2, a0q.z, a1q.z);
                STEP256(R0, R1, Z0, Z1, k4*4+3, a0q.w, a1q.w);
            }
        }
        #pragma unroll
        for (int cc = 0; cc < 4; cc++) {
            float2 r0 = upk(R0[cc]); float2 r1 = upk(R1[cc]);
            float2 z0 = upk(Z0[cc]); float2 z1 = upk(Z1[cc]);
            rs[0][2*cc] = sigm(r0.x); rs[0][2*cc+1] = sigm(r0.y);
            rs[1][2*cc] = sigm(r1.x); rs[1][2*cc+1] = sigm(r1.y);
            zs[0][2*cc] = sigm(z0.x); zs[0][2*cc+1] = sigm(z0.y);
            zs[1][2*cc] = sigm(z1.x); zs[1][2*cc+1] = sigm(z1.y);
        }
    }

    // ======== GRU n : tiles g=32..39, KT=16 ========
    {
        u64t N0[4], N1[4], G0[4], G1[4];
        {
            float4 ni0 = *(const float4*)(gbi + 2*H + c0);
            float4 ni1 = *(const float4*)(gbi + 2*H + c0 + 4);
            float4 nh0 = *(const float4*)(gbh + 2*H + c0);
            float4 nh1 = *(const float4*)(gbh + 2*H + c0 + 4);
            N0[0] = pk2b(ni0.x, ni0.y); N0[1] = pk2b(ni0.z, ni0.w);
            N0[2] = pk2b(ni1.x, ni1.y); N0[3] = pk2b(ni1.z, ni1.w);
            G0[0] = pk2b(nh0.x, nh0.y); G0[1] = pk2b(nh0.z, nh0.w);
            G0[2] = pk2b(nh1.x, nh1.y); G0[3] = pk2b(nh1.z, nh1.w);
            #pragma unroll
            for (int i = 0; i < 4; i++) { N1[i] = N0[i]; G1[i] = G0[i]; }
        }
        #pragma unroll 1
        for (int t = 0; t < 8; t++) {
            int g = 32 + t;
            cpwait0();
            __syncthreads();
            if (t < 7) { stage16k(sbu, (g+1)&1, g_wn + (t+1)*4096, tid); cpcommit(); }
            const float* bw = sB + (g&1)*4096;
            const float4* x0v = (const float4*)(sC + rowA*SC_STR + t*16);
            const float4* x1v = x0v + (8*SC_STR)/4;
            const float4* h0v = x0v + 32;   // +128 floats
            const float4* h1v = x1v + 32;
            #pragma unroll
            for (int k4 = 0; k4 < 4; k4++) {
                float4 x0q = x0v[k4];
                float4 x1q = x1v[k4];
                float4 h0q = h0v[k4];
                float4 h1q = h1v[k4];
                STEPN(k4*4+0, x0q.x, x1q.x, h0q.x, h1q.x);
                STEPN(k4*4+1, x0q.y, x1q.y, h0q.y, h1q.y);
                STEPN(k4*4+2, x0q.z, x1q.z, h0q.z, h1q.z);
                STEPN(k4*4+3, x0q.w, x1q.w, h0q.w, h1q.w);
            }
        }

        // finalize h
        float hv0[8], hv1[8];
        const float* hp0 = sC + rowA*SC_STR + 128 + c0;
        const float* hp1 = hp0 + 8*SC_STR;
        #pragma unroll
        for (int cc = 0; cc < 4; cc++) {
            float2 nv0 = upk(N0[cc]); float2 gv0 = upk(G0[cc]);
            float2 nv1 = upk(N1[cc]); float2 gv1 = upk(G1[cc]);
            float n00 = tanhf(fmaf(rs[0][2*cc],   gv0.x, nv0.x));
            float n01 = tanhf(fmaf(rs[0][2*cc+1], gv0.y, nv0.y));
            float n10 = tanhf(fmaf(rs[1][2*cc],   gv1.x, nv1.x));
            float n11 = tanhf(fmaf(rs[1][2*cc+1], gv1.y, nv1.y));
            hv0[2*cc]   = (1.f - zs[0][2*cc])  * n00 + zs[0][2*cc]  * hp0[2*cc];
            hv0[2*cc+1] = (1.f - zs[0][2*cc+1])* n01 + zs[0][2*cc+1]* hp0[2*cc+1];
            hv1[2*cc]   = (1.f - zs[1][2*cc])  * n10 + zs[1][2*cc]  * hp1[2*cc];
            hv1[2*cc+1] = (1.f - zs[1][2*cc+1])* n11 + zs[1][2*cc+1]* hp1[2*cc+1];
        }
        int r0g = row0 + rowA, r1g = r0g + 8;
        *(float4*)&out[OFF_H + r0g*H + c0]     = make_float4(hv0[0], hv0[1], hv0[2], hv0[3]);
        *(float4*)&out[OFF_H + r0g*H + c0 + 4] = make_float4(hv0[4], hv0[5], hv0[6], hv0[7]);
        *(float4*)&out[OFF_H + r1g*H + c0]     = make_float4(hv1[0], hv1[1], hv1[2], hv1[3]);
        *(float4*)&out[OFF_H + r1g*H + c0 + 4] = make_float4(hv1[4], hv1[5], hv1[6], hv1[7]);

        __syncthreads();           // everyone done reading sC (x2/hp)

        // write h into sC cols [0,128)
        float* ho0 = sC + rowA*SC_STR + c0;
        float* ho1 = ho0 + 8*SC_STR;
        #pragma unroll
        for (int cc = 0; cc < 8; cc++) { ho0[cc] = hv0[cc]; ho1[cc] = hv1[cc]; }
    }

    // ======== epilogue: qphi (phi_w via LDG) + fc2 + transpose + sort ========
    // sB (8192 floats): sQ [16][129] at 0 ; ssq [16][112] at 2176 ;
    //                   sCos [16][68] at 4096 ; sW [128][16] at 5248
    {
        float* sQ   = sB;
        float* ssq  = sB + 2176;
        float* sCos = sB + 4096;
        float* sW   = sB + 5248;

        // cos table + rq out: thread (qq = tid>>3, fb = tid&7)
        {
            int qq = tid >> 3, fb = tid & 7;
            float rqv = __ldg(rq_in + row0 + qq);
            if (fb == 0) out[OFF_RQ + row0 + qq] = rqv;
            #pragma unroll
            for (int u = 0; u < 8; u++) {
                int f = fb*8 + u;
                sCos[qq*68 + f] = cospif((float)f * rqv);
            }
        }
        // stage fc2_w padded
        for (int i = tid; i < H*NA; i += 128) {
            int j = i / NA, na = i - j*NA;
            sW[j*16 + na] = fc2_w[i];
        }
        __syncthreads();

        // qphi: thread (qq, j0 = fb*16), phi_w streamed via LDG
        {
            int qq = tid >> 3, fb = tid & 7;
            int j0 = fb * 16;
            u64t acc[8];
            #pragma unroll
            for (int p = 0; p < 8; p++)
                acc[p] = pk2b(__ldg(phi_b + j0 + 2*p), __ldg(phi_b + j0 + 2*p + 1));
            const float* crow = sCos + qq*68;
            const ulonglong2* pw = (const ulonglong2*)(phi_w + j0);
            #pragma unroll 8
            for (int f = 0; f < QED; f++) {
                u64t c2 = pk2(crow[f]);
                ulonglong2 w01 = __ldg(pw + f*32);
                ulonglong2 w23 = __ldg(pw + f*32 + 1);
                ulonglong2 w45 = __ldg(pw + f*32 + 2);
                ulonglong2 w67 = __ldg(pw + f*32 + 3);
                fma2(acc[0], c2, w01.x); fma2(acc[1], c2, w01.y);
                fma2(acc[2], c2, w23.x); fma2(acc[3], c2, w23.y);
                fma2(acc[4], c2, w45.x); fma2(acc[5], c2, w45.y);
                fma2(acc[6], c2, w67.x); fma2(acc[7], c2, w67.y);
            }
            float* qo = sQ + qq*129 + j0;
            #pragma unroll
            for (int p = 0; p < 8; p++) {
                float2 v = upk(acc[p]);
                qo[2*p]   = fmaxf(v.x, 0.f);
                qo[2*p+1] = fmaxf(v.y, 0.f);
            }
        }
        __syncthreads();

        // fc2: thread (row = tid&15, qi = tid>>4)
        {
            const int row = tid & 15;
            const int qi  = tid >> 4;
            const float* hrow = sC + row*SC_STR;
            const float* qrow = sQ + ((row >> 3)*8 + qi)*129;
            u64t acc[7];
            #pragma unroll
            for (int p = 0; p < 7; p++)
                acc[p] = pk2b(__ldg(fc2_b + 2*p), __ldg(fc2_b + 2*p + 1));
            #pragma unroll 4
            for (int j = 0; j < H; j++) {
                float hq = hrow[j] * qrow[j];
                u64t h2 = pk2(hq);
                const ulonglong2* wp = (const ulonglong2*)(sW + j*16);
                ulonglong2 w0 = wp[0], w1 = wp[1];
                u64t w2 = *(const u64t*)(sW + j*16 + 8);
                u64t w3 = *(const u64t*)(sW + j*16 + 10);
                u64t w4 = *(const u64t*)(sW + j*16 + 12);
                fma2(acc[0], h2, w0.x); fma2(acc[1], h2, w0.y);
                fma2(acc[2], h2, w1.x); fma2(acc[3], h2, w1.y);
                fma2(acc[4], h2, w2);   fma2(acc[5], h2, w3);
                fma2(acc[6], h2, w4);
            }
            #pragma unroll
            for (int p = 0; p < 7; p++) {
                float2 v = upk(acc[p]);
                ssq[row*112 + (2*p)*8   + qi] = v.x;
                ssq[row*112 + (2*p+1)*8 + qi] = v.y;
            }
        }
        __syncthreads();

        // sort: 224 (row,na) pairs
        for (int p = tid; p < ROWS*NA; p += 128) {
            int r = p / NA, na = p - r*NA;
            const float* s = ssq + r*112 + na*8;
            float v[NQ];
            #pragma unroll
            for (int k = 0; k < NQ; k++) v[k] = s[k];
            #pragma unroll
            for (int i = 1; i < NQ; i++) {
                float key = v[i];
                int q = i - 1;
                while (q >= 0 && v[q] > key) { v[q+1] = v[q]; q--; }
                v[q+1] = key;
            }
            float* o = out + OFF_SQ + (row0 + r)*112 + na*8;
            *(float4*)o       = make_float4(v[0], v[1], v[2], v[3]);
            *(float4*)(o + 4) = make_float4(v[4], v[5], v[6], v[7]);
        }
    }
}

// ---------------------------------------------------------------------------
extern "C" void kernel_launch(void* const* d_in, const int* in_sizes, int n_in,
                              void* d_out, int out_size) {
    const float* in        = (const float*)d_in[0];
    const float* hidden    = (const float*)d_in[1];
    const float* rqs       = (const float*)d_in[2];
    const float* fc1_w     = (const float*)d_in[3];
    const float* fc1_b     = (const float*)d_in[4];
    const float* hyp_w1    = (const float*)d_in[5];
    const float* hyp_b1    = (const float*)d_in[6];
    const float* hyp_w2    = (const float*)d_in[7];
    const float* hyp_b2    = (const float*)d_in[8];
    const float* merger_w  = (const float*)d_in[9];
    const float* gru_wi    = (const float*)d_in[10];
    const float* gru_wh    = (const float*)d_in[11];
    const float* gru_bi    = (const float*)d_in[12];
    const float* gru_bh    = (const float*)d_in[13];
    const float* phi_w     = (const float*)d_in[14];
    const float* phi_b     = (const float*)d_in[15];
    const float* fc2_w     = (const float*)d_in[16];
    const float* fc2_b     = (const float*)d_in[17];
    float* out = (float*)d_out;

    static int smem_set = 0;
    if (!smem_set) {
        cudaFuncSetAttribute(k_main, cudaFuncAttributeMaxDynamicSharedMemorySize,
                             SMEM_BYTES);
        smem_set = 1;
    }

    k_main<<<BS/ROWS, 128, SMEM_BYTES>>>(in, hidden, fc1_w, fc1_b,
                                         hyp_w1, hyp_b1, hyp_w2, hyp_b2,
                                         merger_w, gru_wi, gru_wh,
                                         gru_bi, gru_bh,
                                         rqs, phi_w, phi_b, fc2_w, fc2_b, out);
}

// round 15
// speedup vs baseline: 1.2063x; 1.2063x over previous
#include <cuda_runtime.h>
#include <math.h>

// dims
#define E    256
#define H    128
#define NQ   8
#define QED  64
#define HYP  64
#define NA   14
#define BS   4096
#define BSG  512

// output layout: sorted_q [BS,NA,NQ] | h [BS,H] | rq [BSG,NQ]
#define OFF_SQ 0
#define OFF_H  (BS*NA*NQ)
#define OFF_RQ (OFF_H + BS*H)

// scratch weights (built cooperatively by k_main prologue)
__device__ __align__(16) float g_W[H*2*H];        // [128][256]
__device__ __align__(16) float g_wrz[2*H*2*H];    // [256][256]
__device__ __align__(16) float g_wn[H*2*H];       // [128][256]
__device__ unsigned long long g_ctr = 0ULL;       // monotonic epoch counter

typedef unsigned long long u64t;
__device__ __forceinline__ u64t pk2(float a) {
    u64t r; asm("mov.b64 %0, {%1,%1};" : "=l"(r) : "f"(a)); return r;
}
__device__ __forceinline__ u64t pk2b(float a, float b) {
    u64t r; asm("mov.b64 %0, {%1,%2};" : "=l"(r) : "f"(a), "f"(b)); return r;
}
__device__ __forceinline__ void fma2(u64t& d, u64t a, u64t b) {
    asm("fma.rn.f32x2 %0, %1, %2, %3;" : "=l"(d) : "l"(a), "l"(b), "l"(d));
}
__device__ __forceinline__ float2 upk(u64t v) {
    float2 f; asm("mov.b64 {%0,%1}, %2;" : "=f"(f.x), "=f"(f.y) : "l"(v)); return f;
}
__device__ __forceinline__ float sigm(float x) {
    return __fdividef(1.f, 1.f + __expf(-x));
}

// cp.async helpers
__device__ __forceinline__ void cpa16(unsigned s, const void* g) {
    asm volatile("cp.async.cg.shared.global [%0], [%1], 16;" :: "r"(s), "l"(g));
}
__device__ __forceinline__ void cpcommit() { asm volatile("cp.async.commit_group;"); }
__device__ __forceinline__ void cpwait0()  { asm volatile("cp.async.wait_group 0;"); }

// ---------------------------------------------------------------------------
// fused everything. 128 threads, 16 rows/block, 256 blocks, 2 CTAs/SM.
// rowA = lane&7 (rows rowA, rowA+8); c0 = (warp*4 + (lane>>3))*8.
// 20 weight tiles of 32KB, 2 buffers, 1 barrier per tile.
#define ROWS 16
#define SC_STR 260
#define SX_STR 132
#define SC_F (ROWS*SC_STR)
#define SX_F (ROWS*SX_STR)
#define SB_F (2*8192)
#define SMEM_BYTES ((SC_F + SX_F + SB_F)*4)

__device__ __forceinline__ void stage32k(unsigned sbu, int bufi,
                                         const float* src, int tid) {
    unsigned d = sbu + (unsigned)(bufi*32768 + tid*16);
    const char* s = (const char*)src + tid*16;
    #pragma unroll
    for (int i = 0; i < 16; i++) cpa16(d + i*2048, s + i*2048);
}

// dual-row, 128-wide step (fc1)
#define STEP128(KK, A0, A1) { \
    const float* wr_ = bw + (KK)*128 + c0; \
    ulonglong2 w01_ = *(const ulonglong2*)wr_; \
    ulonglong2 w23_ = *(const ulonglong2*)(wr_ + 4); \
    u64t a0_ = pk2(A0), a1_ = pk2(A1); \
    fma2(X0[0], a0_, w01_.x); fma2(X0[1], a0_, w01_.y); \
    fma2(X0[2], a0_, w23_.x); fma2(X0[3], a0_, w23_.y); \
    fma2(X1[0], a1_, w01_.x); fma2(X1[1], a1_, w01_.y); \
    fma2(X1[2], a1_, w23_.x); fma2(X1[3], a1_, w23_.y); }

// dual-row, 256-wide step (emb / gru-rz): halves use same activations
#define STEP256(AC0, AC1, BC0, BC1, KK, A0, A1) { \
    const float* wr_ = bw + (KK)*256 + c0; \
    ulonglong2 p01_ = *(const ulonglong2*)wr_; \
    ulonglong2 p23_ = *(const ulonglong2*)(wr_ + 4); \
    ulonglong2 q01_ = *(const ulonglong2*)(wr_ + 128); \
    ulonglong2 q23_ = *(const ulonglong2*)(wr_ + 132); \
    u64t a0_ = pk2(A0), a1_ = pk2(A1); \
    fma2(AC0[0], a0_, p01_.x); fma2(AC0[1], a0_, p01_.y); \
    fma2(AC0[2], a0_, p23_.x); fma2(AC0[3], a0_, p23_.y); \
    fma2(AC1[0], a1_, p01_.x); fma2(AC1[1], a1_, p01_.y); \
    fma2(AC1[2], a1_, p23_.x); fma2(AC1[3], a1_, p23_.y); \
    fma2(BC0[0], a0_, q01_.x); fma2(BC0[1], a0_, q01_.y); \
    fma2(BC0[2], a0_, q23_.x); fma2(BC0[3], a0_, q23_.y); \
    fma2(BC1[0], a1_, q01_.x); fma2(BC1[1], a1_, q01_.y); \
    fma2(BC1[2], a1_, q23_.x); fma2(BC1[3], a1_, q23_.y); }

// dual-row, 256-wide step (gru-n): p-half uses x2, q-half uses h
#define STEPN(KK, XA0, XA1, HA0, HA1) { \
    const float* wr_ = bw + (KK)*256 + c0; \
    ulonglong2 p01_ = *(const ulonglong2*)wr_; \
    ulonglong2 p23_ = *(const ulonglong2*)(wr_ + 4); \
    ulonglong2 q01_ = *(const ulonglong2*)(wr_ + 128); \
    ulonglong2 q23_ = *(const ulonglong2*)(wr_ + 132); \
    u64t x0_ = pk2(XA0), x1_ = pk2(XA1); \
    u64t h0_ = pk2(HA0), h1_ = pk2(HA1); \
    fma2(N0[0], x0_, p01_.x); fma2(N0[1], x0_, p01_.y); \
    fma2(N0[2], x0_, p23_.x); fma2(N0[3], x0_, p23_.y); \
    fma2(N1[0], x1_, p01_.x); fma2(N1[1], x1_, p01_.y); \
    fma2(N1[2], x1_, p23_.x); fma2(N1[3], x1_, p23_.y); \
    fma2(G0[0], h0_, q01_.x); fma2(G0[1], h0_, q01_.y); \
    fma2(G0[2], h0_, q23_.x); fma2(G0[3], h0_, q23_.y); \
    fma2(G1[0], h1_, q01_.x); fma2(G1[1], h1_, q01_.y); \
    fma2(G1[2], h1_, q23_.x); fma2(G1[3], h1_, q23_.y); }

__global__ __launch_bounds__(128, 2)
void k_main(const float* __restrict__ in, const float* __restrict__ hprev,
            const float* __restrict__ fc1_w, const float* __restrict__ fc1_b,
            const float* __restrict__ hyp_w1, const float* __restrict__ hyp_b1,
            const float* __restrict__ hyp_w2, const float* __restrict__ hyp_b2,
            const float* __restrict__ merger_w,
            const float* __restrict__ gwi,  const float* __restrict__ gwh,
            const float* __restrict__ gbi,  const float* __restrict__ gbh,
            const float* __restrict__ rq_in,
            const float* __restrict__ phi_w, const float* __restrict__ phi_b,
            const float* __restrict__ fc2_w, const float* __restrict__ fc2_b,
            float* __restrict__ out) {
    extern __shared__ float smem[];
    float* sC = smem;
    float* sX = smem + SC_F;
    float* sB = smem + SC_F + SX_F;
    unsigned sbu = (unsigned)__cvta_generic_to_shared(sB);

    const int tid  = threadIdx.x;
    const int lane = tid & 31;
    const int warp = tid >> 5;              // 0..3
    const int rowA = lane & 7;
    const int c0   = (warp*4 + (lane >> 3))*8;   // 0..120
    const int row0 = blockIdx.x * ROWS;

    // ======== distributed weight prep: 1/256 slice per CTA ========
    unsigned long long ticket = 0ULL;
    {
        float* sh = sX;   // 64 floats, consumed before sX is reused for x
        if (tid < HYP) {
            float s = hyp_b1[tid];
            #pragma unroll
            for (int q = 0; q < NQ; q++) s += hyp_w1[q*HYP + tid];
            sh[tid] = fmaxf(s, 0.f);
        }
        __syncthreads();
        {   // buildW: one output per thread
            int m = blockIdx.x*128 + tid;
            float acc = hyp_b2[m];
            #pragma unroll 16
            for (int f = 0; f < HYP; f++) acc = fmaf(sh[f], hyp_w2[f*32768 + m], acc);
            g_W[m] = acc;
        }
        #pragma unroll
        for (int s = 0; s < 2; s++) {       // wrz: 2 per thread
            int idx = blockIdx.x*256 + s*128 + tid;
            int k = idx >> 8, j = idx & 255;
            g_wrz[idx] = (k < 128) ? gwi[j*128 + k] : gwh[j*128 + (k - 128)];
        }
        {   // wn: 1 per thread
            int idx = blockIdx.x*128 + tid;
            int k = idx >> 8, j = idx & 255;
            g_wn[idx] = (j < 128) ? gwi[(256 + j)*128 + k] : gwh[(128 + j)*128 + k];
        }
        __syncthreads();
        if (tid == 0) {
            // release-scoped add: orders this CTA's weight stores before the
            // ticket becomes visible to acquire-side spinners
            asm volatile("atom.release.gpu.global.add.u64 %0, [%1], 1;"
                         : "=l"(ticket) : "l"(&g_ctr) : "memory");
        }
    }

    // prefetch fc1 tile 0 + stage input A [16][256] -> sC
    stage32k(sbu, 0, fc1_w, tid); cpcommit();
    {
        const float4* src = (const float4*)(in + row0*E);
        #pragma unroll
        for (int i = tid; i < 1024; i += 128) {
            float4 v = src[i];
            int f = i * 4;
            int r = f >> 8, cc = f & 255;
            float* p = sC + r*SC_STR + cc;
            p[0] = v.x; p[1] = v.y; p[2] = v.z; p[3] = v.w;
        }
    }

    // ======== FC1 : tiles g=0..3, KT=64, width 128 ========
    u64t X0[4], X1[4];
    {
        float4 b0 = *(const float4*)(fc1_b + c0);
        float4 b1 = *(const float4*)(fc1_b + c0 + 4);
        X0[0] = pk2b(b0.x, b0.y); X0[1] = pk2b(b0.z, b0.w);
        X0[2] = pk2b(b1.x, b1.y); X0[3] = pk2b(b1.z, b1.w);
        X1[0] = X0[0]; X1[1] = X0[1]; X1[2] = X0[2]; X1[3] = X0[3];
    }
    #pragma unroll 1
    for (int t = 0; t < 4; t++) {
        int g = t;
        cpwait0();
        __syncthreads();
        if (t == 3) {   // g_W about to be staged: wait for all CTAs' wprep
            if (tid == 0) {
                unsigned long long target = ((ticket >> 8) + 1) << 8;
                unsigned long long v;
                do {
                    asm volatile("ld.acquire.gpu.global.u64 %0, [%1];"
                                 : "=l"(v) : "l"(&g_ctr));
                } while (v < target);
            }
            __syncthreads();
        }
        const float* nsrc = (t < 3) ? (fc1_w + (t+1)*8192) : g_W;
        stage32k(sbu, (g+1)&1, nsrc, tid); cpcommit();
        const float* bw = sB + (g&1)*8192;
        const float4* a0v = (const float4*)(sC + rowA*SC_STR + t*64);
        const float4* a1v = a0v + (8*SC_STR)/4;
        #pragma unroll 4
        for (int k4 = 0; k4 < 16; k4++) {
            float4 a0q = a0v[k4];
            float4 a1q = a1v[k4];
            STEP128(k4*4+0, a0q.x, a1q.x);
            STEP128(k4*4+1, a0q.y, a1q.y);
            STEP128(k4*4+2, a0q.z, a1q.z);
            STEP128(k4*4+3, a0q.w, a1q.w);
        }
    }
    {
        float* xo0 = sX + rowA*SX_STR + c0;
        float* xo1 = xo0 + 8*SX_STR;
        #pragma unroll
        for (int cc = 0; cc < 4; cc++) {
            float2 v0 = upk(X0[cc]);
            float2 v1 = upk(X1[cc]);
            xo0[2*cc]   = fmaxf(v0.x, 0.f); xo0[2*cc+1] = fmaxf(v0.y, 0.f);
            xo1[2*cc]   = fmaxf(v1.x, 0.f); xo1[2*cc+1] = fmaxf(v1.y, 0.f);
        }
    }

    // ======== EMB : tiles g=4..7, KT=32, width 256 ========
    u64t P0[4] = {0,0,0,0}, P1[4] = {0,0,0,0};
    u64t Q0[4] = {0,0,0,0}, Q1[4] = {0,0,0,0};
    #pragma unroll 1
    for (int t = 0; t < 4; t++) {
        int g = 4 + t;
        cpwait0();
        __syncthreads();
        const float* nsrc = (t < 3) ? (g_W + (t+1)*8192) : g_wrz;
        stage32k(sbu, (g+1)&1, nsrc, tid); cpcommit();
        const float* bw = sB + (g&1)*8192;
        const float4* a0v = (const float4*)(sX + rowA*SX_STR + t*32);
        const float4* a1v = a0v + (8*SX_STR)/4;
        #pragma unroll 4
        for (int k4 = 0; k4 < 8; k4++) {
            float4 a0q = a0v[k4];
            float4 a1q = a1v[k4];
            STEP256(P0, P1, Q0, Q1, k4*4+0, a0q.x, a1q.x);
            STEP256(P0, P1, Q0, Q1, k4*4+1, a0q.y, a1q.y);
            STEP256(P0, P1, Q0, Q1, k4*4+2, a0q.z, a1q.z);
            STEP256(P0, P1, Q0, Q1, k4*4+3, a0q.w, a1q.w);
        }
    }

    // ---- merge (inline msm) + relu -> x2 into sC[0,128); stage hprev -> sC[128,256)
    {
        float m0v[8], m1v[8];
        #pragma unroll
        for (int cc = 0; cc < 8; cc++) {
            float a = merger_w[c0 + cc], b = merger_w[H + c0 + cc];
            float m = fmaxf(a, b);
            float e0 = expf(a - m), e1 = expf(b - m);
            float inv = 1.f / (e0 + e1);
            m0v[cc] = e0 * inv;
            m1v[cc] = e1 * inv;
        }
        float* co0 = sC + rowA*SC_STR + c0;
        float* co1 = co0 + 8*SC_STR;
        #pragma unroll
        for (int cc = 0; cc < 4; cc++) {
            float2 a0 = upk(P0[cc]); float2 b0 = upk(Q0[cc]);
            float2 a1 = upk(P1[cc]); float2 b1 = upk(Q1[cc]);
            co0[2*cc]   = fmaxf(fmaf(m0v[2*cc],   a0.x, m1v[2*cc]  *b0.x), 0.f);
            co0[2*cc+1] = fmaxf(fmaf(m0v[2*cc+1], a0.y, m1v[2*cc+1]*b0.y), 0.f);
            co1[2*cc]   = fmaxf(fmaf(m0v[2*cc],   a1.x, m1v[2*cc]  *b1.x), 0.f);
            co1[2*cc+1] = fmaxf(fmaf(m0v[2*cc+1], a1.y, m1v[2*cc+1]*b1.y), 0.f);
        }
        const float4* hsrc = (const float4*)(hprev + row0*H);
        #pragma unroll
        for (int i = tid; i < 512; i += 128) {
            float4 v = hsrc[i];
            int f = i * 4;
            int r = f >> 7, cc = f & 127;
            float* p = sC + r*SC_STR + 128 + cc;
            p[0] = v.x; p[1] = v.y; p[2] = v.z; p[3] = v.w;
        }
    }

    // ======== GRU r,z : tiles g=8..15, KT=32, width 256 ========
    float rs[2][8], zs[2][8];
    {
        u64t R0[4], R1[4], Z0[4], Z1[4];
        {
            float4 bi0 = *(const float4*)(gbi + c0);
            float4 bi1 = *(const float4*)(gbi + c0 + 4);
            float4 bh0 = *(const float4*)(gbh + c0);
            float4 bh1 = *(const float4*)(gbh + c0 + 4);
            R0[0] = pk2b(bi0.x+bh0.x, bi0.y+bh0.y);
            R0[1] = pk2b(bi0.z+bh0.z, bi0.w+bh0.w);
            R0[2] = pk2b(bi1.x+bh1.x, bi1.y+bh1.y);
            R0[3] = pk2b(bi1.z+bh1.z, bi1.w+bh1.w);
            float4 ci0 = *(const float4*)(gbi + H + c0);
            float4 ci1 = *(const float4*)(gbi + H + c0 + 4);
            float4 ch0 = *(const float4*)(gbh + H + c0);
            float4 ch1 = *(const float4*)(gbh + H + c0 + 4);
            Z0[0] = pk2b(ci0.x+ch0.x, ci0.y+ch0.y);
            Z0[1] = pk2b(ci0.z+ch0.z, ci0.w+ch0.w);
            Z0[2] = pk2b(ci1.x+ch1.x, ci1.y+ch1.y);
            Z0[3] = pk2b(ci1.z+ch1.z, ci1.w+ch1.w);
            #pragma unroll
            for (int i = 0; i < 4; i++) { R1[i] = R0[i]; Z1[i] = Z0[i]; }
        }
        #pragma unroll 1
        for (int t = 0; t < 8; t++) {
            int g = 8 + t;
            cpwait0();
            __syncthreads();
            const float* nsrc = (t < 7) ? (g_wrz + (t+1)*8192) : g_wn;
            stage32k(sbu, (g+1)&1, nsrc, tid); cpcommit();
            const float* bw = sB + (g&1)*8192;
            const float4* a0v = (const float4*)(sC + rowA*SC_STR + t*32);
            const float4* a1v = a0v + (8*SC_STR)/4;
            #pragma unroll 4
            for (int k4 = 0; k4 < 8; k4++) {
                float4 a0q = a0v[k4];
                float4 a1q = a1v[k4];
                STEP256(R0, R1, Z0, Z1, k4*4+0, a0q.x, a1q.x);
                STEP256(R0, R1, Z0, Z1, k4*4+1, a0q.y, a1q.y);
                STEP256(R0, R1, Z0, Z1, k4*4+2, a0q.z, a1q.z);
                STEP256(R0, R1, Z0, Z1, k4*4+3, a0q.w, a1q.w);
            }
        }
        #pragma unroll
        for (int cc = 0; cc < 4; cc++) {
            float2 r0 = upk(R0[cc]); float2 r1 = upk(R1[cc]);
            float2 z0 = upk(Z0[cc]); float2 z1 = upk(Z1[cc]);
            rs[0][2*cc] = sigm(r0.x); rs[0][2*cc+1] = sigm(r0.y);
            rs[1][2*cc] = sigm(r1.x); rs[1][2*cc+1] = sigm(r1.y);
            zs[0][2*cc] = sigm(z0.x); zs[0][2*cc+1] = sigm(z0.y);
            zs[1][2*cc] = sigm(z1.x); zs[1][2*cc+1] = sigm(z1.y);
        }
    }

    // ======== GRU n : tiles g=16..19, KT=32 ========
    {
        u64t N0[4], N1[4], G0[4], G1[4];
        {
            float4 ni0 = *(const float4*)(gbi + 2*H + c0);
            float4 ni1 = *(const float4*)(gbi + 2*H + c0 + 4);
            float4 nh0 = *(const float4*)(gbh + 2*H + c0);
            float4 nh1 = *(const float4*)(gbh + 2*H + c0 + 4);
            N0[0] = pk2b(ni0.x, ni0.y); N0[1] = pk2b(ni0.z, ni0.w);
            N0[2] = pk2b(ni1.x, ni1.y); N0[3] = pk2b(ni1.z, ni1.w);
            G0[0] = pk2b(nh0.x, nh0.y); G0[1] = pk2b(nh0.z, nh0.w);
            G0[2] = pk2b(nh1.x, nh1.y); G0[3] = pk2b(nh1.z, nh1.w);
            #pragma unroll
            for (int i = 0; i < 4; i++) { N1[i] = N0[i]; G1[i] = G0[i]; }
        }
        #pragma unroll 1
        for (int t = 0; t < 4; t++) {
            int g = 16 + t;
            cpwait0();
            __syncthreads();
            if (t < 3) { stage32k(sbu, (g+1)&1, g_wn + (t+1)*8192, tid); cpcommit(); }
            const float* bw = sB + (g&1)*8192;
            const float4* x0v = (const float4*)(sC + rowA*SC_STR + t*32);
            const float4* x1v = x0v + (8*SC_STR)/4;
            const float4* h0v = x0v + 32;   // +128 floats
            const float4* h1v = x1v + 32;
            #pragma unroll 4
            for (int k4 = 0; k4 < 8; k4++) {
                float4 x0q = x0v[k4];
                float4 x1q = x1v[k4];
                float4 h0q = h0v[k4];
                float4 h1q = h1v[k4];
                STEPN(k4*4+0, x0q.x, x1q.x, h0q.x, h1q.x);
                STEPN(k4*4+1, x0q.y, x1q.y, h0q.y, h1q.y);
                STEPN(k4*4+2, x0q.z, x1q.z, h0q.z, h1q.z);
                STEPN(k4*4+3, x0q.w, x1q.w, h0q.w, h1q.w);
            }
        }

        // finalize h
        float hv0[8], hv1[8];
        const float* hp0 = sC + rowA*SC_STR + 128 + c0;
        const float* hp1 = hp0 + 8*SC_STR;
        #pragma unroll
        for (int cc = 0; cc < 4; cc++) {
            float2 nv0 = upk(N0[cc]); float2 gv0 = upk(G0[cc]);
            float2 nv1 = upk(N1[cc]); float2 gv1 = upk(G1[cc]);
            float n00 = tanhf(fmaf(rs[0][2*cc],   gv0.x, nv0.x));
            float n01 = tanhf(fmaf(rs[0][2*cc+1], gv0.y, nv0.y));
            float n10 = tanhf(fmaf(rs[1][2*cc],   gv1.x, nv1.x));
            float n11 = tanhf(fmaf(rs[1][2*cc+1], gv1.y, nv1.y));
            hv0[2*cc]   = (1.f - zs[0][2*cc])  * n00 + zs[0][2*cc]  * hp0[2*cc];
            hv0[2*cc+1] = (1.f - zs[0][2*cc+1])* n01 + zs[0][2*cc+1]* hp0[2*cc+1];
            hv1[2*cc]   = (1.f - zs[1][2*cc])  * n10 + zs[1][2*cc]  * hp1[2*cc];
            hv1[2*cc+1] = (1.f - zs[1][2*cc+1])* n11 + zs[1][2*cc+1]* hp1[2*cc+1];
        }
        int r0g = row0 + rowA, r1g = r0g + 8;
        *(float4*)&out[OFF_H + r0g*H + c0]     = make_float4(hv0[0], hv0[1], hv0[2], hv0[3]);
        *(float4*)&out[OFF_H + r0g*H + c0 + 4] = make_float4(hv0[4], hv0[5], hv0[6], hv0[7]);
        *(float4*)&out[OFF_H + r1g*H + c0]     = make_float4(hv1[0], hv1[1], hv1[2], hv1[3]);
        *(float4*)&out[OFF_H + r1g*H + c0 + 4] = make_float4(hv1[4], hv1[5], hv1[6], hv1[7]);

        __syncthreads();           // everyone done reading sC (x2/hp)

        // write h into sC cols [0,128)
        float* ho0 = sC + rowA*SC_STR + c0;
        float* ho1 = ho0 + 8*SC_STR;
        #pragma unroll
        for (int cc = 0; cc < 8; cc++) { ho0[cc] = hv0[cc]; ho1[cc] = hv1[cc]; }
    }

    // ======== epilogue: qphi + fc2 + transpose + sort ========
    // sB: sQ [16][129] at 0 ; ssq [16][112] at 2176 ;
    //     sPhi [64][160 swz] at 4096 ; sCos [16][68] at 14336
    // sX: sW fc2_w padded [128][16]
    {
        float* sQ   = sB;
        float* ssq  = sB + 2176;
        float* sPhi = sB + 4096;      // stride 160, j' = j + 4*(j>>4)
        float* sCos = sB + 14336;     // stride 68
        float* sW   = sX;

        // cos table + rq out: thread (qq = tid>>3, fb = tid&7)
        {
            int qq = tid >> 3, fb = tid & 7;
            float rqv = __ldg(rq_in + row0 + qq);
            if (fb == 0) out[OFF_RQ + row0 + qq] = rqv;
            #pragma unroll
            for (int u = 0; u < 8; u++) {
                int f = fb*8 + u;
                sCos[qq*68 + f] = cospif((float)f * rqv);
            }
        }
        // stage phi_w swizzled + fc2_w padded
        #pragma unroll
        for (int i = tid; i < 2048; i += 128) {
            float4 v = ((const float4*)phi_w)[i];
            int f = i >> 5, jt = (i & 31)*4;
            float* p = sPhi + f*160 + jt + ((jt >> 4) << 2);
            p[0] = v.x; p[1] = v.y; p[2] = v.z; p[3] = v.w;
        }
        for (int i = tid; i < H*NA; i += 128) {
            int j = i / NA, na = i - j*NA;
            sW[j*16 + na] = fc2_w[i];
        }
        __syncthreads();

        // qphi: thread (qq = tid>>3, j0 = (tid&7)*16) -> 16 outputs
        {
            int qq = tid >> 3, fb = tid & 7;
            int j0 = fb * 16;
            const float* ph = sPhi + j0 + 4*fb;    // swizzled column base
            u64t acc[8];
            #pragma unroll
            for (int p = 0; p < 8; p++)
                acc[p] = pk2b(phi_b[j0 + 2*p], phi_b[j0 + 2*p + 1]);
            const float* crow = sCos + qq*68;
            #pragma unroll 8
            for (int f = 0; f < QED; f++) {
                u64t c2 = pk2(crow[f]);
                const float* pr = ph + f*160;
                ulonglong2 w01 = *(const ulonglong2*)pr;
                ulonglong2 w23 = *(const ulonglong2*)(pr + 4);
                ulonglong2 w45 = *(const ulonglong2*)(pr + 8);
                ulonglong2 w67 = *(const ulonglong2*)(pr + 12);
                fma2(acc[0], c2, w01.x); fma2(acc[1], c2, w01.y);
                fma2(acc[2], c2, w23.x); fma2(acc[3], c2, w23.y);
                fma2(acc[4], c2, w45.x); fma2(acc[5], c2, w45.y);
                fma2(acc[6], c2, w67.x); fma2(acc[7], c2, w67.y);
            }
            float* qo = sQ + qq*129 + j0;
            #pragma unroll
            for (int p = 0; p < 8; p++) {
                float2 v = upk(acc[p]);
                qo[2*p]   = fmaxf(v.x, 0.f);
                qo[2*p+1] = fmaxf(v.y, 0.f);
            }
        }
        __syncthreads();

        // fc2: thread (row = tid&15, qi = tid>>4)
        {
            const int row = tid & 15;
            const int qi  = tid >> 4;
            const float* hrow = sC + row*SC_STR;
            const float* qrow = sQ + ((row >> 3)*8 + qi)*129;
            u64t acc[7];
            #pragma unroll
            for (int p = 0; p < 7; p++) acc[p] = pk2b(fc2_b[2*p], fc2_b[2*p+1]);
            #pragma unroll 4
            for (int j = 0; j < H; j++) {
                float hq = hrow[j] * qrow[j];
                u64t h2 = pk2(hq);
                const ulonglong2* wp = (const ulonglong2*)(sW + j*16);
                ulonglong2 w0 = wp[0], w1 = wp[1];
                u64t w2 = *(const u64t*)(sW + j*16 + 8);
                u64t w3 = *(const u64t*)(sW + j*16 + 10);
                u64t w4 = *(const u64t*)(sW + j*16 + 12);
                fma2(acc[0], h2, w0.x); fma2(acc[1], h2, w0.y);
                fma2(acc[2], h2, w1.x); fma2(acc[3], h2, w1.y);
                fma2(acc[4], h2, w2);   fma2(acc[5], h2, w3);
                fma2(acc[6], h2, w4);
            }
            #pragma unroll
            for (int p = 0; p < 7; p++) {
                float2 v = upk(acc[p]);
                ssq[row*112 + (2*p)*8   + qi] = v.x;
                ssq[row*112 + (2*p+1)*8 + qi] = v.y;
            }
        }
        __syncthreads();

        // sort: 224 (row,na) pairs
        for (int p = tid; p < ROWS*NA; p += 128) {
            int r = p / NA, na = p - r*NA;
            const float* s = ssq + r*112 + na*8;
            float v[NQ];
            #pragma unroll
            for (int k = 0; k < NQ; k++) v[k] = s[k];
            #pragma unroll
            for (int i = 1; i < NQ; i++) {
                float key = v[i];
                int q = i - 1;
                while (q >= 0 && v[q] > key) { v[q+1] = v[q]; q--; }
                v[q+1] = key;
            }
            float* o = out + OFF_SQ + (row0 + r)*112 + na*8;
            *(float4*)o       = make_float4(v[0], v[1], v[2], v[3]);
            *(float4*)(o + 4) = make_float4(v[4], v[5], v[6], v[7]);
        }
    }
}

// ---------------------------------------------------------------------------
extern "C" void kernel_launch(void* const* d_in, const int* in_sizes, int n_in,
                              void* d_out, int out_size) {
    const float* in        = (const float*)d_in[0];
    const float* hidden    = (const float*)d_in[1];
    const float* rqs       = (const float*)d_in[2];
    const float* fc1_w     = (const float*)d_in[3];
    const float* fc1_b     = (const float*)d_in[4];
    const float* hyp_w1    = (const float*)d_in[5];
    const float* hyp_b1    = (const float*)d_in[6];
    const float* hyp_w2    = (const float*)d_in[7];
    const float* hyp_b2    = (const float*)d_in[8];
    const float* merger_w  = (const float*)d_in[9];
    const float* gru_wi    = (const float*)d_in[10];
    const float* gru_wh    = (const float*)d_in[11];
    const float* gru_bi    = (const float*)d_in[12];
    const float* gru_bh    = (const float*)d_in[13];
    const float* phi_w     = (const float*)d_in[14];
    const float* phi_b     = (const float*)d_in[15];
    const float* fc2_w     = (const float*)d_in[16];
    const float* fc2_b     = (const float*)d_in[17];
    float* out = (float*)d_out;

    static int smem_set = 0;
    if (!smem_set) {
        cudaFuncSetAttribute(k_main, cudaFuncAttributeMaxDynamicSharedMemorySize,
                             SMEM_BYTES);
        smem_set = 1;
    }

    k_main<<<BS/ROWS, 128, SMEM_BYTES>>>(in, hidden, fc1_w, fc1_b,
                                         hyp_w1, hyp_b1, hyp_w2, hyp_b2,
                                         merger_w, gru_wi, gru_wh,
                                         gru_bi, gru_bh,
                                         rqs, phi_w, phi_b, fc2_w, fc2_b, out);
}

// round 16
// speedup vs baseline: 1.2483x; 1.0348x over previous
#include <cuda_runtime.h>
#include <math.h>

// dims
#define E    256
#define H    128
#define NQ   8
#define QED  64
#define HYP  64
#define NA   14
#define BS   4096
#define BSG  512

// output layout: sorted_q [BS,NA,NQ] | h [BS,H] | rq [BSG,NQ]
#define OFF_SQ 0
#define OFF_H  (BS*NA*NQ)
#define OFF_RQ (OFF_H + BS*H)

// scratch weights (built cooperatively by k_main prologue)
__device__ __align__(16) float g_W[H*2*H];        // [128][256]
__device__ __align__(16) float g_wrz[2*H*2*H];    // [256][256]
__device__ __align__(16) float g_wn[H*2*H];       // [128][256]
__device__ unsigned long long g_ctr = 0ULL;       // monotonic epoch counter

typedef unsigned long long u64t;
__device__ __forceinline__ u64t pk2(float a) {
    u64t r; asm("mov.b64 %0, {%1,%1};" : "=l"(r) : "f"(a)); return r;
}
__device__ __forceinline__ u64t pk2b(float a, float b) {
    u64t r; asm("mov.b64 %0, {%1,%2};" : "=l"(r) : "f"(a), "f"(b)); return r;
}
__device__ __forceinline__ void fma2(u64t& d, u64t a, u64t b) {
    asm("fma.rn.f32x2 %0, %1, %2, %3;" : "=l"(d) : "l"(a), "l"(b), "l"(d));
}
__device__ __forceinline__ float2 upk(u64t v) {
    float2 f; asm("mov.b64 {%0,%1}, %2;" : "=f"(f.x), "=f"(f.y) : "l"(v)); return f;
}
__device__ __forceinline__ float sigm(float x) {
    return __fdividef(1.f, 1.f + __expf(-x));
}

// mbarrier + bulk-copy helpers
#define MB_INIT(a, c) \
    asm volatile("mbarrier.init.shared.b64 [%0], %1;" :: "r"(a), "r"(c) : "memory")
#define MB_EXPECT(a, b) \
    asm volatile("mbarrier.arrive.expect_tx.shared.b64 _, [%0], %1;" \
                 :: "r"(a), "r"(b) : "memory")
#define BULK_G2S(d, s, n, b) \
    asm volatile("cp.async.bulk.shared::cta.global.mbarrier::complete_tx::bytes " \
                 "[%0], [%1], %2, [%3];" \
                 :: "r"(d), "l"(s), "r"(n), "r"(b) : "memory")
#define MB_WAIT(a, par) do { \
    unsigned _m = (a); unsigned _p = (par); unsigned _done; \
    asm volatile("{\n\t.reg .pred p;\n\t" \
        "mbarrier.try_wait.parity.acquire.cta.shared::cta.b64 p, [%1], %2;\n\t" \
        "selp.b32 %0, 1, 0, p;\n\t}" : "=r"(_done) : "r"(_m), "r"(_p) : "memory"); \
    if (!_done) { \
        asm volatile("{\n\t.reg .pred P1;\n\t" \
            "WL_%=:\n\t" \
            "mbarrier.try_wait.parity.acquire.cta.shared::cta.b64 P1, [%0], %1, 0x989680;\n\t" \
            "@P1 bra.uni WD_%=;\n\t" \
            "bra.uni WL_%=;\n\t" \
            "WD_%=:\n\t}" :: "r"(_m), "r"(_p) : "memory"); \
    } \
} while (0)

// ---------------------------------------------------------------------------
// fused everything. 128 threads, 16 rows/block, 256 blocks, 2 CTAs/SM.
// rowA = lane&7 (rows rowA, rowA+8); c0 = (warp*4 + (lane>>3))*8.
// 20 weight tiles of 32KB, 2 buffers, staged via cp.async.bulk + mbarrier.
#define ROWS 16
#define SC_STR 260
#define SX_STR 132
#define SC_F (ROWS*SC_STR)
#define SX_F (ROWS*SX_STR)
#define SB_F (2*8192)
#define SMEM_BYTES ((SC_F + SX_F + SB_F + 4)*4)

// dual-row, 128-wide step (fc1)
#define STEP128(KK, A0, A1) { \
    const float* wr_ = bw + (KK)*128 + c0; \
    ulonglong2 w01_ = *(const ulonglong2*)wr_; \
    ulonglong2 w23_ = *(const ulonglong2*)(wr_ + 4); \
    u64t a0_ = pk2(A0), a1_ = pk2(A1); \
    fma2(X0[0], a0_, w01_.x); fma2(X0[1], a0_, w01_.y); \
    fma2(X0[2], a0_, w23_.x); fma2(X0[3], a0_, w23_.y); \
    fma2(X1[0], a1_, w01_.x); fma2(X1[1], a1_, w01_.y); \
    fma2(X1[2], a1_, w23_.x); fma2(X1[3], a1_, w23_.y); }

// dual-row, 256-wide step (emb / gru-rz): halves use same activations
#define STEP256(AC0, AC1, BC0, BC1, KK, A0, A1) { \
    const float* wr_ = bw + (KK)*256 + c0; \
    ulonglong2 p01_ = *(const ulonglong2*)wr_; \
    ulonglong2 p23_ = *(const ulonglong2*)(wr_ + 4); \
    ulonglong2 q01_ = *(const ulonglong2*)(wr_ + 128); \
    ulonglong2 q23_ = *(const ulonglong2*)(wr_ + 132); \
    u64t a0_ = pk2(A0), a1_ = pk2(A1); \
    fma2(AC0[0], a0_, p01_.x); fma2(AC0[1], a0_, p01_.y); \
    fma2(AC0[2], a0_, p23_.x); fma2(AC0[3], a0_, p23_.y); \
    fma2(AC1[0], a1_, p01_.x); fma2(AC1[1], a1_, p01_.y); \
    fma2(AC1[2], a1_, p23_.x); fma2(AC1[3], a1_, p23_.y); \
    fma2(BC0[0], a0_, q01_.x); fma2(BC0[1], a0_, q01_.y); \
    fma2(BC0[2], a0_, q23_.x); fma2(BC0[3], a0_, q23_.y); \
    fma2(BC1[0], a1_, q01_.x); fma2(BC1[1], a1_, q01_.y); \
    fma2(BC1[2], a1_, q23_.x); fma2(BC1[3], a1_, q23_.y); }

// dual-row, 256-wide step (gru-n): p-half uses x2, q-half uses h
#define STEPN(KK, XA0, XA1, HA0, HA1) { \
    const float* wr_ = bw + (KK)*256 + c0; \
    ulonglong2 p01_ = *(const ulonglong2*)wr_; \
    ulonglong2 p23_ = *(const ulonglong2*)(wr_ + 4); \
    ulonglong2 q01_ = *(const ulonglong2*)(wr_ + 128); \
    ulonglong2 q23_ = *(const ulonglong2*)(wr_ + 132); \
    u64t x0_ = pk2(XA0), x1_ = pk2(XA1); \
    u64t h0_ = pk2(HA0), h1_ = pk2(HA1); \
    fma2(N0[0], x0_, p01_.x); fma2(N0[1], x0_, p01_.y); \
    fma2(N0[2], x0_, p23_.x); fma2(N0[3], x0_, p23_.y); \
    fma2(N1[0], x1_, p01_.x); fma2(N1[1], x1_, p01_.y); \
    fma2(N1[2], x1_, p23_.x); fma2(N1[3], x1_, p23_.y); \
    fma2(G0[0], h0_, q01_.x); fma2(G0[1], h0_, q01_.y); \
    fma2(G0[2], h0_, q23_.x); fma2(G0[3], h0_, q23_.y); \
    fma2(G1[0], h1_, q01_.x); fma2(G1[1], h1_, q01_.y); \
    fma2(G1[2], h1_, q23_.x); fma2(G1[3], h1_, q23_.y); }

__device__ __forceinline__ const float* tile_src(int g, const float* fc1_w) {
    if (g < 4)  return fc1_w + g*8192;
    if (g < 8)  return g_W   + (g-4)*8192;
    if (g < 16) return g_wrz + (g-8)*8192;
    return g_wn + (g-16)*8192;
}

// producer: tid0 stages tile gn (if valid); spins for cross-CTA wprep before tile 4
#define STAGE_NEXT(GN) \
    if (tid == 0 && (GN) < 20) { \
        if ((GN) == 4) { \
            unsigned long long target = ((ticket >> 8) + 1) << 8; \
            unsigned long long v_; \
            do { asm volatile("ld.acquire.gpu.global.u64 %0, [%1];" \
                              : "=l"(v_) : "l"(&g_ctr)); } while (v_ < target); \
        } \
        unsigned mb_ = mbu + ((GN)&1)*8; \
        MB_EXPECT(mb_, 32768); \
        BULK_G2S(sbu + ((GN)&1)*32768, tile_src((GN), fc1_w), 32768, mb_); \
    }

__global__ __launch_bounds__(128, 2)
void k_main(const float* __restrict__ in, const float* __restrict__ hprev,
            const float* __restrict__ fc1_w, const float* __restrict__ fc1_b,
            const float* __restrict__ hyp_w1, const float* __restrict__ hyp_b1,
            const float* __restrict__ hyp_w2, const float* __restrict__ hyp_b2,
            const float* __restrict__ merger_w,
            const float* __restrict__ gwi,  const float* __restrict__ gwh,
            const float* __restrict__ gbi,  const float* __restrict__ gbh,
            const float* __restrict__ rq_in,
            const float* __restrict__ phi_w, const float* __restrict__ phi_b,
            const float* __restrict__ fc2_w, const float* __restrict__ fc2_b,
            float* __restrict__ out) {
    extern __shared__ float smem[];
    float* sC = smem;
    float* sX = smem + SC_F;
    float* sB = smem + SC_F + SX_F;
    unsigned sbu = (unsigned)__cvta_generic_to_shared(sB);
    unsigned mbu = sbu + 2*32768;          // 2 mbarriers after the buffers

    const int tid  = threadIdx.x;
    const int lane = tid & 31;
    const int warp = tid >> 5;              // 0..3
    const int rowA = lane & 7;
    const int c0   = (warp*4 + (lane >> 3))*8;   // 0..120
    const int row0 = blockIdx.x * ROWS;

    // ======== distributed weight prep: 1/256 slice per CTA ========
    unsigned long long ticket = 0ULL;
    {
        float* sh = sX;   // 64 floats, consumed before sX is reused for x
        if (tid < HYP) {
            float s = hyp_b1[tid];
            #pragma unroll
            for (int q = 0; q < NQ; q++) s += hyp_w1[q*HYP + tid];
            sh[tid] = fmaxf(s, 0.f);
        }
        __syncthreads();
        {   // buildW: one output per thread
            int m = blockIdx.x*128 + tid;
            float acc = hyp_b2[m];
            #pragma unroll 16
            for (int f = 0; f < HYP; f++) acc = fmaf(sh[f], hyp_w2[f*32768 + m], acc);
            g_W[m] = acc;
        }
        #pragma unroll
        for (int s = 0; s < 2; s++) {       // wrz: 2 per thread
            int idx = blockIdx.x*256 + s*128 + tid;
            int k = idx >> 8, j = idx & 255;
            g_wrz[idx] = (k < 128) ? gwi[j*128 + k] : gwh[j*128 + (k - 128)];
        }
        {   // wn: 1 per thread
            int idx = blockIdx.x*128 + tid;
            int k = idx >> 8, j = idx & 255;
            g_wn[idx] = (j < 128) ? gwi[(256 + j)*128 + k] : gwh[(128 + j)*128 + k];
        }
        __syncthreads();
        if (tid == 0) {
            asm volatile("atom.release.gpu.global.add.u64 %0, [%1], 1;"
                         : "=l"(ticket) : "l"(&g_ctr) : "memory");
            MB_INIT(mbu, 1);
            MB_INIT(mbu + 8, 1);
        }
    }

    // stage input A [16][256] -> sC
    {
        const float4* src = (const float4*)(in + row0*E);
        #pragma unroll
        for (int i = tid; i < 1024; i += 128) {
            float4 v = src[i];
            int f = i * 4;
            int r = f >> 8, cc = f & 255;
            float* p = sC + r*SC_STR + cc;
            p[0] = v.x; p[1] = v.y; p[2] = v.z; p[3] = v.w;
        }
    }
    __syncthreads();          // mbarrier init + input visible
    STAGE_NEXT(0);            // prefetch tile 0

    // ======== FC1 : tiles g=0..3, KT=64, width 128 ========
    u64t X0[4], X1[4];
    {
        float4 b0 = *(const float4*)(fc1_b + c0);
        float4 b1 = *(const float4*)(fc1_b + c0 + 4);
        X0[0] = pk2b(b0.x, b0.y); X0[1] = pk2b(b0.z, b0.w);
        X0[2] = pk2b(b1.x, b1.y); X0[3] = pk2b(b1.z, b1.w);
        X1[0] = X0[0]; X1[1] = X0[1]; X1[2] = X0[2]; X1[3] = X0[3];
    }
    #pragma unroll 1
    for (int t = 0; t < 4; t++) {
        int g = t;
        __syncthreads();                      // prior consumer of buf (g+1)&1 done
        STAGE_NEXT(g + 1);
        MB_WAIT(mbu + (g&1)*8, (g>>1)&1);     // tile g arrived
        const float* bw = sB + (g&1)*8192;
        const float4* a0v = (const float4*)(sC + rowA*SC_STR + t*64);
        const float4* a1v = a0v + (8*SC_STR)/4;
        #pragma unroll 4
        for (int k4 = 0; k4 < 16; k4++) {
            float4 a0q = a0v[k4];
            float4 a1q = a1v[k4];
            STEP128(k4*4+0, a0q.x, a1q.x);
            STEP128(k4*4+1, a0q.y, a1q.y);
            STEP128(k4*4+2, a0q.z, a1q.z);
            STEP128(k4*4+3, a0q.w, a1q.w);
        }
    }
    {
        float* xo0 = sX + rowA*SX_STR + c0;
        float* xo1 = xo0 + 8*SX_STR;
        #pragma unroll
        for (int cc = 0; cc < 4; cc++) {
            float2 v0 = upk(X0[cc]);
            float2 v1 = upk(X1[cc]);
            xo0[2*cc]   = fmaxf(v0.x, 0.f); xo0[2*cc+1] = fmaxf(v0.y, 0.f);
            xo1[2*cc]   = fmaxf(v1.x, 0.f); xo1[2*cc+1] = fmaxf(v1.y, 0.f);
        }
    }

    // ======== EMB : tiles g=4..7, KT=32, width 256 ========
    u64t P0[4] = {0,0,0,0}, P1[4] = {0,0,0,0};
    u64t Q0[4] = {0,0,0,0}, Q1[4] = {0,0,0,0};
    #pragma unroll 1
    for (int t = 0; t < 4; t++) {
        int g = 4 + t;
        __syncthreads();
        STAGE_NEXT(g + 1);
        MB_WAIT(mbu + (g&1)*8, (g>>1)&1);
        const float* bw = sB + (g&1)*8192;
        const float4* a0v = (const float4*)(sX + rowA*SX_STR + t*32);
        const float4* a1v = a0v + (8*SX_STR)/4;
        #pragma unroll 4
        for (int k4 = 0; k4 < 8; k4++) {
            float4 a0q = a0v[k4];
            float4 a1q = a1v[k4];
            STEP256(P0, P1, Q0, Q1, k4*4+0, a0q.x, a1q.x);
            STEP256(P0, P1, Q0, Q1, k4*4+1, a0q.y, a1q.y);
            STEP256(P0, P1, Q0, Q1, k4*4+2, a0q.z, a1q.z);
            STEP256(P0, P1, Q0, Q1, k4*4+3, a0q.w, a1q.w);
        }
    }

    // ---- merge (inline msm) + relu -> x2 into sC[0,128); stage hprev -> sC[128,256)
    {
        float m0v[8], m1v[8];
        #pragma unroll
        for (int cc = 0; cc < 8; cc++) {
            float a = merger_w[c0 + cc], b = merger_w[H + c0 + cc];
            float m = fmaxf(a, b);
            float e0 = expf(a - m), e1 = expf(b - m);
            float inv = 1.f / (e0 + e1);
            m0v[cc] = e0 * inv;
            m1v[cc] = e1 * inv;
        }
        float* co0 = sC + rowA*SC_STR + c0;
        float* co1 = co0 + 8*SC_STR;
        #pragma unroll
        for (int cc = 0; cc < 4; cc++) {
            float2 a0 = upk(P0[cc]); float2 b0 = upk(Q0[cc]);
            float2 a1 = upk(P1[cc]); float2 b1 = upk(Q1[cc]);
            co0[2*cc]   = fmaxf(fmaf(m0v[2*cc],   a0.x, m1v[2*cc]  *b0.x), 0.f);
            co0[2*cc+1] = fmaxf(fmaf(m0v[2*cc+1], a0.y, m1v[2*cc+1]*b0.y), 0.f);
            co1[2*cc]   = fmaxf(fmaf(m0v[2*cc],   a1.x, m1v[2*cc]  *b1.x), 0.f);
            co1[2*cc+1] = fmaxf(fmaf(m0v[2*cc+1], a1.y, m1v[2*cc+1]*b1.y), 0.f);
        }
        const float4* hsrc = (const float4*)(hprev + row0*H);
        #pragma unroll
        for (int i = tid; i < 512; i += 128) {
            float4 v = hsrc[i];
            int f = i * 4;
            int r = f >> 7, cc = f & 127;
            float* p = sC + r*SC_STR + 128 + cc;
            p[0] = v.x; p[1] = v.y; p[2] = v.z; p[3] = v.w;
        }
    }

    // ======== GRU r,z : tiles g=8..15, KT=32, width 256 ========
    float rs[2][8], zs[2][8];
    {
        u64t R0[4], R1[4], Z0[4], Z1[4];
        {
            float4 bi0 = *(const float4*)(gbi + c0);
            float4 bi1 = *(const float4*)(gbi + c0 + 4);
            float4 bh0 = *(const float4*)(gbh + c0);
            float4 bh1 = *(const float4*)(gbh + c0 + 4);
            R0[0] = pk2b(bi0.x+bh0.x, bi0.y+bh0.y);
            R0[1] = pk2b(bi0.z+bh0.z, bi0.w+bh0.w);
            R0[2] = pk2b(bi1.x+bh1.x, bi1.y+bh1.y);
            R0[3] = pk2b(bi1.z+bh1.z, bi1.w+bh1.w);
            float4 ci0 = *(const float4*)(gbi + H + c0);
            float4 ci1 = *(const float4*)(gbi + H + c0 + 4);
            float4 ch0 = *(const float4*)(gbh + H + c0);
            float4 ch1 = *(const float4*)(gbh + H + c0 + 4);
            Z0[0] = pk2b(ci0.x+ch0.x, ci0.y+ch0.y);
            Z0[1] = pk2b(ci0.z+ch0.z, ci0.w+ch0.w);
            Z0[2] = pk2b(ci1.x+ch1.x, ci1.y+ch1.y);
            Z0[3] = pk2b(ci1.z+ch1.z, ci1.w+ch1.w);
            #pragma unroll
            for (int i = 0; i < 4; i++) { R1[i] = R0[i]; Z1[i] = Z0[i]; }
        }
        #pragma unroll 1
        for (int t = 0; t < 8; t++) {
            int g = 8 + t;
            __syncthreads();
            STAGE_NEXT(g + 1);
            MB_WAIT(mbu + (g&1)*8, (g>>1)&1);
            const float* bw = sB + (g&1)*8192;
            const float4* a0v = (const float4*)(sC + rowA*SC_STR + t*32);
            const float4* a1v = a0v + (8*SC_STR)/4;
            #pragma unroll 4
            for (int k4 = 0; k4 < 8; k4++) {
                float4 a0q = a0v[k4];
                float4 a1q = a1v[k4];
                STEP256(R0, R1, Z0, Z1, k4*4+0, a0q.x, a1q.x);
                STEP256(R0, R1, Z0, Z1, k4*4+1, a0q.y, a1q.y);
                STEP256(R0, R1, Z0, Z1, k4*4+2, a0q.z, a1q.z);
                STEP256(R0, R1, Z0, Z1, k4*4+3, a0q.w, a1q.w);
            }
        }
        #pragma unroll
        for (int cc = 0; cc < 4; cc++) {
            float2 r0 = upk(R0[cc]); float2 r1 = upk(R1[cc]);
            float2 z0 = upk(Z0[cc]); float2 z1 = upk(Z1[cc]);
            rs[0][2*cc] = sigm(r0.x); rs[0][2*cc+1] = sigm(r0.y);
            rs[1][2*cc] = sigm(r1.x); rs[1][2*cc+1] = sigm(r1.y);
            zs[0][2*cc] = sigm(z0.x); zs[0][2*cc+1] = sigm(z0.y);
            zs[1][2*cc] = sigm(z1.x); zs[1][2*cc+1] = sigm(z1.y);
        }
    }

    // ======== GRU n : tiles g=16..19, KT=32 ========
    {
        u64t N0[4], N1[4], G0[4], G1[4];
        {
            float4 ni0 = *(const float4*)(gbi + 2*H + c0);
            float4 ni1 = *(const float4*)(gbi + 2*H + c0 + 4);
            float4 nh0 = *(const float4*)(gbh + 2*H + c0);
            float4 nh1 = *(const float4*)(gbh + 2*H + c0 + 4);
            N0[0] = pk2b(ni0.x, ni0.y); N0[1] = pk2b(ni0.z, ni0.w);
            N0[2] = pk2b(ni1.x, ni1.y); N0[3] = pk2b(ni1.z, ni1.w);
            G0[0] = pk2b(nh0.x, nh0.y); G0[1] = pk2b(nh0.z, nh0.w);
            G0[2] = pk2b(nh1.x, nh1.y); G0[3] = pk2b(nh1.z, nh1.w);
            #pragma unroll
            for (int i = 0; i < 4; i++) { N1[i] = N0[i]; G1[i] = G0[i]; }
        }
        #pragma unroll 1
        for (int t = 0; t < 4; t++) {
            int g = 16 + t;
            __syncthreads();
            STAGE_NEXT(g + 1);
            MB_WAIT(mbu + (g&1)*8, (g>>1)&1);
            const float* bw = sB + (g&1)*8192;
            const float4* x0v = (const float4*)(sC + rowA*SC_STR + t*32);
            const float4* x1v = x0v + (8*SC_STR)/4;
            const float4* h0v = x0v + 32;   // +128 floats
            const float4* h1v = x1v + 32;
            #pragma unroll 4
            for (int k4 = 0; k4 < 8; k4++) {
                float4 x0q = x0v[k4];
                float4 x1q = x1v[k4];
                float4 h0q = h0v[k4];
                float4 h1q = h1v[k4];
                STEPN(k4*4+0, x0q.x, x1q.x, h0q.x, h1q.x);
                STEPN(k4*4+1, x0q.y, x1q.y, h0q.y, h1q.y);
                STEPN(k4*4+2, x0q.z, x1q.z, h0q.z, h1q.z);
                STEPN(k4*4+3, x0q.w, x1q.w, h0q.w, h1q.w);
            }
        }

        // finalize h
        float hv0[8], hv1[8];
        const float* hp0 = sC + rowA*SC_STR + 128 + c0;
        const float* hp1 = hp0 + 8*SC_STR;
        #pragma unroll
        for (int cc = 0; cc < 4; cc++) {
            float2 nv0 = upk(N0[cc]); float2 gv0 = upk(G0[cc]);
            float2 nv1 = upk(N1[cc]); float2 gv1 = upk(G1[cc]);
            float n00 = tanhf(fmaf(rs[0][2*cc],   gv0.x, nv0.x));
            float n01 = tanhf(fmaf(rs[0][2*cc+1], gv0.y, nv0.y));
            float n10 = tanhf(fmaf(rs[1][2*cc],   gv1.x, nv1.x));
            float n11 = tanhf(fmaf(rs[1][2*cc+1], gv1.y, nv1.y));
            hv0[2*cc]   = (1.f - zs[0][2*cc])  * n00 + zs[0][2*cc]  * hp0[2*cc];
            hv0[2*cc+1] = (1.f - zs[0][2*cc+1])* n01 + zs[0][2*cc+1]* hp0[2*cc+1];
            hv1[2*cc]   = (1.f - zs[1][2*cc])  * n10 + zs[1][2*cc]  * hp1[2*cc];
            hv1[2*cc+1] = (1.f - zs[1][2*cc+1])* n11 + zs[1][2*cc+1]* hp1[2*cc+1];
        }
        int r0g = row0 + rowA, r1g = r0g + 8;
        *(float4*)&out[OFF_H + r0g*H + c0]     = make_float4(hv0[0], hv0[1], hv0[2], hv0[3]);
        *(float4*)&out[OFF_H + r0g*H + c0 + 4] = make_float4(hv0[4], hv0[5], hv0[6], hv0[7]);
        *(float4*)&out[OFF_H + r1g*H + c0]     = make_float4(hv1[0], hv1[1], hv1[2], hv1[3]);
        *(float4*)&out[OFF_H + r1g*H + c0 + 4] = make_float4(hv1[4], hv1[5], hv1[6], hv1[7]);

        __syncthreads();           // everyone done reading sC (x2/hp) + tile 19

        // write h into sC cols [0,128)
        float* ho0 = sC + rowA*SC_STR + c0;
        float* ho1 = ho0 + 8*SC_STR;
        #pragma unroll
        for (int cc = 0; cc < 8; cc++) { ho0[cc] = hv0[cc]; ho1[cc] = hv1[cc]; }
    }

    // ======== epilogue: qphi + fc2 + transpose + sort ========
    // sB: sQ [16][129] at 0 ; ssq [16][112] at 2176 ;
    //     sPhi [64][160 swz] at 4096 ; sCos [16][68] at 14336
    // sX: sW fc2_w padded [128][16]
    {
        float* sQ   = sB;
        float* ssq  = sB + 2176;
        float* sPhi = sB + 4096;      // stride 160, j' = j + 4*(j>>4)
        float* sCos = sB + 14336;     // stride 68
        float* sW   = sX;

        // cos table + rq out: thread (qq = tid>>3, fb = tid&7)
        {
            int qq = tid >> 3, fb = tid & 7;
            float rqv = __ldg(rq_in + row0 + qq);
            if (fb == 0) out[OFF_RQ + row0 + qq] = rqv;
            #pragma unroll
            for (int u = 0; u < 8; u++) {
                int f = fb*8 + u;
                sCos[qq*68 + f] = cospif((float)f * rqv);
            }
        }
        // stage phi_w swizzled + fc2_w padded
        #pragma unroll
        for (int i = tid; i < 2048; i += 128) {
            float4 v = ((const float4*)phi_w)[i];
            int f = i >> 5, jt = (i & 31)*4;
            float* p = sPhi + f*160 + jt + ((jt >> 4) << 2);
            p[0] = v.x; p[1] = v.y; p[2] = v.z; p[3] = v.w;
        }
        for (int i = tid; i < H*NA; i += 128) {
            int j = i / NA, na = i - j*NA;
            sW[j*16 + na] = fc2_w[i];
        }
        __syncthreads();

        // qphi: thread (qq = tid>>3, j0 = (tid&7)*16) -> 16 outputs
        {
            int qq = tid >> 3, fb = tid & 7;
            int j0 = fb * 16;
            const float* ph = sPhi + j0 + 4*fb;    // swizzled column base
            u64t acc[8];
            #pragma unroll
            for (int p = 0; p < 8; p++)
                acc[p] = pk2b(phi_b[j0 + 2*p], phi_b[j0 + 2*p + 1]);
            const float* crow = sCos + qq*68;
            #pragma unroll 8
            for (int f = 0; f < QED; f++) {
                u64t c2 = pk2(crow[f]);
                const float* pr = ph + f*160;
                ulonglong2 w01 = *(const ulonglong2*)pr;
                ulonglong2 w23 = *(const ulonglong2*)(pr + 4);
                ulonglong2 w45 = *(const ulonglong2*)(pr + 8);
                ulonglong2 w67 = *(const ulonglong2*)(pr + 12);
                fma2(acc[0], c2, w01.x); fma2(acc[1], c2, w01.y);
                fma2(acc[2], c2, w23.x); fma2(acc[3], c2, w23.y);
                fma2(acc[4], c2, w45.x); fma2(acc[5], c2, w45.y);
                fma2(acc[6], c2, w67.x); fma2(acc[7], c2, w67.y);
            }
            float* qo = sQ + qq*129 + j0;
            #pragma unroll
            for (int p = 0; p < 8; p++) {
                float2 v = upk(acc[p]);
                qo[2*p]   = fmaxf(v.x, 0.f);
                qo[2*p+1] = fmaxf(v.y, 0.f);
            }
        }
        __syncthreads();

        // fc2: thread (row = tid&15, qi = tid>>4)
        {
            const int row = tid & 15;
            const int qi  = tid >> 4;
            const float* hrow = sC + row*SC_STR;
            const float* qrow = sQ + ((row >> 3)*8 + qi)*129;
            u64t acc[7];
            #pragma unroll
            for (int p = 0; p < 7; p++) acc[p] = pk2b(fc2_b[2*p], fc2_b[2*p+1]);
            #pragma unroll 4
            for (int j = 0; j < H; j++) {
                float hq = hrow[j] * qrow[j];
                u64t h2 = pk2(hq);
                const ulonglong2* wp = (const ulonglong2*)(sW + j*16);
                ulonglong2 w0 = wp[0], w1 = wp[1];
                u64t w2 = *(const u64t*)(sW + j*16 + 8);
                u64t w3 = *(const u64t*)(sW + j*16 + 10);
                u64t w4 = *(const u64t*)(sW + j*16 + 12);
                fma2(acc[0], h2, w0.x); fma2(acc[1], h2, w0.y);
                fma2(acc[2], h2, w1.x); fma2(acc[3], h2, w1.y);
                fma2(acc[4], h2, w2);   fma2(acc[5], h2, w3);
                fma2(acc[6], h2, w4);
            }
            #pragma unroll
            for (int p = 0; p < 7; p++) {
                float2 v = upk(acc[p]);
                ssq[row*112 + (2*p)*8   + qi] = v.x;
                ssq[row*112 + (2*p+1)*8 + qi] = v.y;
            }
        }
        __syncthreads();

        // sort: 224 (row,na) pairs
        for (int p = tid; p < ROWS*NA; p += 128) {
            int r = p / NA, na = p - r*NA;
            const float* s = ssq + r*112 + na*8;
            float v[NQ];
            #pragma unroll
            for (int k = 0; k < NQ; k++) v[k] = s[k];
            #pragma unroll
            for (int i = 1; i < NQ; i++) {
                float key = v[i];
                int q = i - 1;
                while (q >= 0 && v[q] > key) { v[q+1] = v[q]; q--; }
                v[q+1] = key;
            }
            float* o = out + OFF_SQ + (row0 + r)*112 + na*8;
            *(float4*)o       = make_float4(v[0], v[1], v[2], v[3]);
            *(float4*)(o + 4) = make_float4(v[4], v[5], v[6], v[7]);
        }
    }
}

// ---------------------------------------------------------------------------
extern "C" void kernel_launch(void* const* d_in, const int* in_sizes, int n_in,
                              void* d_out, int out_size) {
    const float* in        = (const float*)d_in[0];
    const float* hidden    = (const float*)d_in[1];
    const float* rqs       = (const float*)d_in[2];
    const float* fc1_w     = (const float*)d_in[3];
    const float* fc1_b     = (const float*)d_in[4];
    const float* hyp_w1    = (const float*)d_in[5];
    const float* hyp_b1    = (const float*)d_in[6];
    const float* hyp_w2    = (const float*)d_in[7];
    const float* hyp_b2    = (const float*)d_in[8];
    const float* merger_w  = (const float*)d_in[9];
    const float* gru_wi    = (const float*)d_in[10];
    const float* gru_wh    = (const float*)d_in[11];
    const float* gru_bi    = (const float*)d_in[12];
    const float* gru_bh    = (const float*)d_in[13];
    const float* phi_w     = (const float*)d_in[14];
    const float* phi_b     = (const float*)d_in[15];
    const float* fc2_w     = (const float*)d_in[16];
    const float* fc2_b     = (const float*)d_in[17];
    float* out = (float*)d_out;

    static int smem_set = 0;
    if (!smem_set) {
        cudaFuncSetAttribute(k_main, cudaFuncAttributeMaxDynamicSharedMemorySize,
                             SMEM_BYTES);
        smem_set = 1;
    }

    k_main<<<BS/ROWS, 128, SMEM_BYTES>>>(in, hidden, fc1_w, fc1_b,
                                         hyp_w1, hyp_b1, hyp_w2, hyp_b2,
                                         merger_w, gru_wi, gru_wh,
                                         gru_bi, gru_bh,
                                         rqs, phi_w, phi_b, fc2_w, fc2_b, out);
}

// round 17
// speedup vs baseline: 1.2637x; 1.0123x over previous
#include <cuda_runtime.h>
#include <math.h>

// dims
#define E    256
#define H    128
#define NQ   8
#define QED  64
#define HYP  64
#define NA   14
#define BS   4096
#define BSG  512

// output layout: sorted_q [BS,NA,NQ] | h [BS,H] | rq [BSG,NQ]
#define OFF_SQ 0
#define OFF_H  (BS*NA*NQ)
#define OFF_RQ (OFF_H + BS*H)

// scratch weights (built cooperatively by k_main prologue)
__device__ __align__(16) float g_W[H*2*H];        // [128][256]
__device__ __align__(16) float g_wrz[2*H*2*H];    // [256][256]
__device__ __align__(16) float g_wn[H*2*H];       // [128][256]
__device__ unsigned long long g_ctr = 0ULL;       // monotonic epoch counter

typedef unsigned long long u64t;
__device__ __forceinline__ u64t pk2(float a) {
    u64t r; asm("mov.b64 %0, {%1,%1};" : "=l"(r) : "f"(a)); return r;
}
__device__ __forceinline__ u64t pk2b(float a, float b) {
    u64t r; asm("mov.b64 %0, {%1,%2};" : "=l"(r) : "f"(a), "f"(b)); return r;
}
__device__ __forceinline__ void fma2(u64t& d, u64t a, u64t b) {
    asm("fma.rn.f32x2 %0, %1, %2, %3;" : "=l"(d) : "l"(a), "l"(b), "l"(d));
}
__device__ __forceinline__ float2 upk(u64t v) {
    float2 f; asm("mov.b64 {%0,%1}, %2;" : "=f"(f.x), "=f"(f.y) : "l"(v)); return f;
}
__device__ __forceinline__ float sigm(float x) {
    return __fdividef(1.f, 1.f + __expf(-x));
}

// mbarrier + bulk-copy helpers
#define MB_INIT(a, c) \
    asm volatile("mbarrier.init.shared.b64 [%0], %1;" :: "r"(a), "r"(c) : "memory")
#define MB_EXPECT(a, b) \
    asm volatile("mbarrier.arrive.expect_tx.shared.b64 _, [%0], %1;" \
                 :: "r"(a), "r"(b) : "memory")
#define BULK_G2S(d, s, n, b) \
    asm volatile("cp.async.bulk.shared::cta.global.mbarrier::complete_tx::bytes " \
                 "[%0], [%1], %2, [%3];" \
                 :: "r"(d), "l"(s), "r"(n), "r"(b) : "memory")
#define MB_WAIT(a, par) do { \
    unsigned _m = (a); unsigned _p = (par); unsigned _done; \
    asm volatile("{\n\t.reg .pred p;\n\t" \
        "mbarrier.try_wait.parity.acquire.cta.shared::cta.b64 p, [%1], %2;\n\t" \
        "selp.b32 %0, 1, 0, p;\n\t}" : "=r"(_done) : "r"(_m), "r"(_p) : "memory"); \
    if (!_done) { \
        asm volatile("{\n\t.reg .pred P1;\n\t" \
            "WL_%=:\n\t" \
            "mbarrier.try_wait.parity.acquire.cta.shared::cta.b64 P1, [%0], %1, 0x989680;\n\t" \
            "@P1 bra.uni WD_%=;\n\t" \
            "bra.uni WL_%=;\n\t" \
            "WD_%=:\n\t}" :: "r"(_m), "r"(_p) : "memory"); \
    } \
} while (0)

// ---------------------------------------------------------------------------
// fused everything. 128 threads, 16 rows/block, 256 blocks, 2 CTAs/SM.
// rowA = lane&7 (rows rowA, rowA+8); c0 = (warp*4 + (lane>>3))*8.
// 20 weight tiles of 32KB, 2 buffers, staged via cp.async.bulk + mbarrier.
#define ROWS 16
#define SC_STR 260
#define SX_STR 132
#define SC_F (ROWS*SC_STR)
#define SX_F (ROWS*SX_STR)
#define SB_F (2*8192)
#define SMEM_BYTES ((SC_F + SX_F + SB_F + 4)*4)

// dual-row, 128-wide step (fc1)
#define STEP128(KK, A0, A1) { \
    const float* wr_ = bw + (KK)*128 + c0; \
    ulonglong2 w01_ = *(const ulonglong2*)wr_; \
    ulonglong2 w23_ = *(const ulonglong2*)(wr_ + 4); \
    u64t a0_ = pk2(A0), a1_ = pk2(A1); \
    fma2(X0[0], a0_, w01_.x); fma2(X0[1], a0_, w01_.y); \
    fma2(X0[2], a0_, w23_.x); fma2(X0[3], a0_, w23_.y); \
    fma2(X1[0], a1_, w01_.x); fma2(X1[1], a1_, w01_.y); \
    fma2(X1[2], a1_, w23_.x); fma2(X1[3], a1_, w23_.y); }

// dual-row, 256-wide step (emb / gru-rz): halves use same activations
#define STEP256(AC0, AC1, BC0, BC1, KK, A0, A1) { \
    const float* wr_ = bw + (KK)*256 + c0; \
    ulonglong2 p01_ = *(const ulonglong2*)wr_; \
    ulonglong2 p23_ = *(const ulonglong2*)(wr_ + 4); \
    ulonglong2 q01_ = *(const ulonglong2*)(wr_ + 128); \
    ulonglong2 q23_ = *(const ulonglong2*)(wr_ + 132); \
    u64t a0_ = pk2(A0), a1_ = pk2(A1); \
    fma2(AC0[0], a0_, p01_.x); fma2(AC0[1], a0_, p01_.y); \
    fma2(AC0[2], a0_, p23_.x); fma2(AC0[3], a0_, p23_.y); \
    fma2(AC1[0], a1_, p01_.x); fma2(AC1[1], a1_, p01_.y); \
    fma2(AC1[2], a1_, p23_.x); fma2(AC1[3], a1_, p23_.y); \
    fma2(BC0[0], a0_, q01_.x); fma2(BC0[1], a0_, q01_.y); \
    fma2(BC0[2], a0_, q23_.x); fma2(BC0[3], a0_, q23_.y); \
    fma2(BC1[0], a1_, q01_.x); fma2(BC1[1], a1_, q01_.y); \
    fma2(BC1[2], a1_, q23_.x); fma2(BC1[3], a1_, q23_.y); }

// dual-row, 256-wide step (gru-n): p-half uses x2, q-half uses h
#define STEPN(KK, XA0, XA1, HA0, HA1) { \
    const float* wr_ = bw + (KK)*256 + c0; \
    ulonglong2 p01_ = *(const ulonglong2*)wr_; \
    ulonglong2 p23_ = *(const ulonglong2*)(wr_ + 4); \
    ulonglong2 q01_ = *(const ulonglong2*)(wr_ + 128); \
    ulonglong2 q23_ = *(const ulonglong2*)(wr_ + 132); \
    u64t x0_ = pk2(XA0), x1_ = pk2(XA1); \
    u64t h0_ = pk2(HA0), h1_ = pk2(HA1); \
    fma2(N0[0], x0_, p01_.x); fma2(N0[1], x0_, p01_.y); \
    fma2(N0[2], x0_, p23_.x); fma2(N0[3], x0_, p23_.y); \
    fma2(N1[0], x1_, p01_.x); fma2(N1[1], x1_, p01_.y); \
    fma2(N1[2], x1_, p23_.x); fma2(N1[3], x1_, p23_.y); \
    fma2(G0[0], h0_, q01_.x); fma2(G0[1], h0_, q01_.y); \
    fma2(G0[2], h0_, q23_.x); fma2(G0[3], h0_, q23_.y); \
    fma2(G1[0], h1_, q01_.x); fma2(G1[1], h1_, q01_.y); \
    fma2(G1[2], h1_, q23_.x); fma2(G1[3], h1_, q23_.y); }

__device__ __forceinline__ const float* tile_src(int g, const float* fc1_w) {
    if (g < 4)  return fc1_w + g*8192;
    if (g < 8)  return g_W   + (g-4)*8192;
    if (g < 16) return g_wrz + (g-8)*8192;
    return g_wn + (g-16)*8192;
}

// producer: tid0 stages tile gn (if valid); spins for cross-CTA wprep before tile 4
#define STAGE_NEXT(GN) \
    if (tid == 0 && (GN) < 20) { \
        if ((GN) == 4) { \
            unsigned long long target = ((ticket >> 8) + 1) << 8; \
            unsigned long long v_; \
            do { asm volatile("ld.acquire.gpu.global.u64 %0, [%1];" \
                              : "=l"(v_) : "l"(&g_ctr)); } while (v_ < target); \
        } \
        unsigned mb_ = mbu + ((GN)&1)*8; \
        MB_EXPECT(mb_, 32768); \
        BULK_G2S(sbu + ((GN)&1)*32768, tile_src((GN), fc1_w), 32768, mb_); \
    }

__global__ __launch_bounds__(128, 2)
void k_main(const float* __restrict__ in, const float* __restrict__ hprev,
            const float* __restrict__ fc1_w, const float* __restrict__ fc1_b,
            const float* __restrict__ hyp_w1, const float* __restrict__ hyp_b1,
            const float* __restrict__ hyp_w2, const float* __restrict__ hyp_b2,
            const float* __restrict__ merger_w,
            const float* __restrict__ gwi,  const float* __restrict__ gwh,
            const float* __restrict__ gbi,  const float* __restrict__ gbh,
            const float* __restrict__ rq_in,
            const float* __restrict__ phi_w, const float* __restrict__ phi_b,
            const float* __restrict__ fc2_w, const float* __restrict__ fc2_b,
            float* __restrict__ out) {
    extern __shared__ float smem[];
    float* sC = smem;
    float* sX = smem + SC_F;
    float* sB = smem + SC_F + SX_F;
    unsigned sbu = (unsigned)__cvta_generic_to_shared(sB);
    unsigned mbu = sbu + 2*32768;          // 2 mbarriers after the buffers

    const int tid  = threadIdx.x;
    const int lane = tid & 31;
    const int warp = tid >> 5;              // 0..3
    const int rowA = lane & 7;
    const int c0   = (warp*4 + (lane >> 3))*8;   // 0..120
    const int row0 = blockIdx.x * ROWS;

    // ---- mbarrier init + tile-0 DMA launch FIRST (overlaps with wprep) ----
    if (tid == 0) { MB_INIT(mbu, 1); MB_INIT(mbu + 8, 1); }
    __syncthreads();
    if (tid == 0) {
        MB_EXPECT(mbu, 32768);
        BULK_G2S(sbu, fc1_w, 32768, mbu);     // tile 0
    }

    // stage input A [16][256] -> sC (overlaps tile-0 DMA)
    {
        const float4* src = (const float4*)(in + row0*E);
        #pragma unroll
        for (int i = tid; i < 1024; i += 128) {
            float4 v = src[i];
            int f = i * 4;
            int r = f >> 8, cc = f & 255;
            float* p = sC + r*SC_STR + cc;
            p[0] = v.x; p[1] = v.y; p[2] = v.z; p[3] = v.w;
        }
    }

    // ======== distributed weight prep: 1/256 slice per CTA ========
    unsigned long long ticket = 0ULL;
    {
        float* sh = sX;   // 64 floats, consumed before sX is reused for x
        if (tid < HYP) {
            float s = hyp_b1[tid];
            #pragma unroll
            for (int q = 0; q < NQ; q++) s += hyp_w1[q*HYP + tid];
            sh[tid] = fmaxf(s, 0.f);
        }
        __syncthreads();
        {   // buildW: one output per thread
            int m = blockIdx.x*128 + tid;
            float acc = hyp_b2[m];
            #pragma unroll 16
            for (int f = 0; f < HYP; f++) acc = fmaf(sh[f], hyp_w2[f*32768 + m], acc);
            g_W[m] = acc;
        }
        #pragma unroll
        for (int s = 0; s < 2; s++) {       // wrz: 2 per thread
            int idx = blockIdx.x*256 + s*128 + tid;
            int k = idx >> 8, j = idx & 255;
            g_wrz[idx] = (k < 128) ? gwi[j*128 + k] : gwh[j*128 + (k - 128)];
        }
        {   // wn: 1 per thread
            int idx = blockIdx.x*128 + tid;
            int k = idx >> 8, j = idx & 255;
            g_wn[idx] = (j < 128) ? gwi[(256 + j)*128 + k] : gwh[(128 + j)*128 + k];
        }
        __syncthreads();
        if (tid == 0) {
            asm volatile("atom.release.gpu.global.add.u64 %0, [%1], 1;"
                         : "=l"(ticket) : "l"(&g_ctr) : "memory");
        }
    }
    __syncthreads();          // input + wprep visible

    // ======== FC1 : tiles g=0..3, KT=64, width 128 ========
    u64t X0[4], X1[4];
    {
        float4 b0 = *(const float4*)(fc1_b + c0);
        float4 b1 = *(const float4*)(fc1_b + c0 + 4);
        X0[0] = pk2b(b0.x, b0.y); X0[1] = pk2b(b0.z, b0.w);
        X0[2] = pk2b(b1.x, b1.y); X0[3] = pk2b(b1.z, b1.w);
        X1[0] = X0[0]; X1[1] = X0[1]; X1[2] = X0[2]; X1[3] = X0[3];
    }
    #pragma unroll 1
    for (int t = 0; t < 4; t++) {
        int g = t;
        if (t) __syncthreads();               // prior consumer of buf (g+1)&1 done
        STAGE_NEXT(g + 1);
        MB_WAIT(mbu + (g&1)*8, (g>>1)&1);     // tile g arrived
        const float* bw = sB + (g&1)*8192;
        const float4* a0v = (const float4*)(sC + rowA*SC_STR + t*64);
        const float4* a1v = a0v + (8*SC_STR)/4;
        #pragma unroll
        for (int k4 = 0; k4 < 16; k4++) {
            float4 a0q = a0v[k4];
            float4 a1q = a1v[k4];
            STEP128(k4*4+0, a0q.x, a1q.x);
            STEP128(k4*4+1, a0q.y, a1q.y);
            STEP128(k4*4+2, a0q.z, a1q.z);
            STEP128(k4*4+3, a0q.w, a1q.w);
        }
    }
    {
        float* xo0 = sX + rowA*SX_STR + c0;
        float* xo1 = xo0 + 8*SX_STR;
        #pragma unroll
        for (int cc = 0; cc < 4; cc++) {
            float2 v0 = upk(X0[cc]);
            float2 v1 = upk(X1[cc]);
            xo0[2*cc]   = fmaxf(v0.x, 0.f); xo0[2*cc+1] = fmaxf(v0.y, 0.f);
            xo1[2*cc]   = fmaxf(v1.x, 0.f); xo1[2*cc+1] = fmaxf(v1.y, 0.f);
        }
    }

    // ======== EMB : tiles g=4..7, KT=32, width 256 ========
    u64t P0[4] = {0,0,0,0}, P1[4] = {0,0,0,0};
    u64t Q0[4] = {0,0,0,0}, Q1[4] = {0,0,0,0};
    #pragma unroll 1
    for (int t = 0; t < 4; t++) {
        int g = 4 + t;
        __syncthreads();
        STAGE_NEXT(g + 1);
        MB_WAIT(mbu + (g&1)*8, (g>>1)&1);
        const float* bw = sB + (g&1)*8192;
        const float4* a0v = (const float4*)(sX + rowA*SX_STR + t*32);
        const float4* a1v = a0v + (8*SX_STR)/4;
        #pragma unroll
        for (int k4 = 0; k4 < 8; k4++) {
            float4 a0q = a0v[k4];
            float4 a1q = a1v[k4];
            STEP256(P0, P1, Q0, Q1, k4*4+0, a0q.x, a1q.x);
            STEP256(P0, P1, Q0, Q1, k4*4+1, a0q.y, a1q.y);
            STEP256(P0, P1, Q0, Q1, k4*4+2, a0q.z, a1q.z);
            STEP256(P0, P1, Q0, Q1, k4*4+3, a0q.w, a1q.w);
        }
    }

    // ---- merge (inline msm) + relu -> x2 into sC[0,128); stage hprev -> sC[128,256)
    {
        float m0v[8], m1v[8];
        #pragma unroll
        for (int cc = 0; cc < 8; cc++) {
            float a = merger_w[c0 + cc], b = merger_w[H + c0 + cc];
            float m = fmaxf(a, b);
            float e0 = expf(a - m), e1 = expf(b - m);
            float inv = 1.f / (e0 + e1);
            m0v[cc] = e0 * inv;
            m1v[cc] = e1 * inv;
        }
        float* co0 = sC + rowA*SC_STR + c0;
        float* co1 = co0 + 8*SC_STR;
        #pragma unroll
        for (int cc = 0; cc < 4; cc++) {
            float2 a0 = upk(P0[cc]); float2 b0 = upk(Q0[cc]);
            float2 a1 = upk(P1[cc]); float2 b1 = upk(Q1[cc]);
            co0[2*cc]   = fmaxf(fmaf(m0v[2*cc],   a0.x, m1v[2*cc]  *b0.x), 0.f);
            co0[2*cc+1] = fmaxf(fmaf(m0v[2*cc+1], a0.y, m1v[2*cc+1]*b0.y), 0.f);
            co1[2*cc]   = fmaxf(fmaf(m0v[2*cc],   a1.x, m1v[2*cc]  *b1.x), 0.f);
            co1[2*cc+1] = fmaxf(fmaf(m0v[2*cc+1], a1.y, m1v[2*cc+1]*b1.y), 0.f);
        }
        const float4* hsrc = (const float4*)(hprev + row0*H);
        #pragma unroll
        for (int i = tid; i < 512; i += 128) {
            float4 v = hsrc[i];
            int f = i * 4;
            int r = f >> 7, cc = f & 127;
            float* p = sC + r*SC_STR + 128 + cc;
            p[0] = v.x; p[1] = v.y; p[2] = v.z; p[3] = v.w;
        }
    }

    // ======== GRU r,z : tiles g=8..15, KT=32, width 256 ========
    float rs[2][8], zs[2][8];
    {
        u64t R0[4], R1[4], Z0[4], Z1[4];
        {
            float4 bi0 = *(const float4*)(gbi + c0);
            float4 bi1 = *(const float4*)(gbi + c0 + 4);
            float4 bh0 = *(const float4*)(gbh + c0);
            float4 bh1 = *(const float4*)(gbh + c0 + 4);
            R0[0] = pk2b(bi0.x+bh0.x, bi0.y+bh0.y);
            R0[1] = pk2b(bi0.z+bh0.z, bi0.w+bh0.w);
            R0[2] = pk2b(bi1.x+bh1.x, bi1.y+bh1.y);
            R0[3] = pk2b(bi1.z+bh1.z, bi1.w+bh1.w);
            float4 ci0 = *(const float4*)(gbi + H + c0);
            float4 ci1 = *(const float4*)(gbi + H + c0 + 4);
            float4 ch0 = *(const float4*)(gbh + H + c0);
            float4 ch1 = *(const float4*)(gbh + H + c0 + 4);
            Z0[0] = pk2b(ci0.x+ch0.x, ci0.y+ch0.y);
            Z0[1] = pk2b(ci0.z+ch0.z, ci0.w+ch0.w);
            Z0[2] = pk2b(ci1.x+ch1.x, ci1.y+ch1.y);
            Z0[3] = pk2b(ci1.z+ch1.z, ci1.w+ch1.w);
            #pragma unroll
            for (int i = 0; i < 4; i++) { R1[i] = R0[i]; Z1[i] = Z0[i]; }
        }
        #pragma unroll 1
        for (int t = 0; t < 8; t++) {
            int g = 8 + t;
            __syncthreads();
            STAGE_NEXT(g + 1);
            MB_WAIT(mbu + (g&1)*8, (g>>1)&1);
            const float* bw = sB + (g&1)*8192;
            const float4* a0v = (const float4*)(sC + rowA*SC_STR + t*32);
            const float4* a1v = a0v + (8*SC_STR)/4;
            #pragma unroll
            for (int k4 = 0; k4 < 8; k4++) {
                float4 a0q = a0v[k4];
                float4 a1q = a1v[k4];
                STEP256(R0, R1, Z0, Z1, k4*4+0, a0q.x, a1q.x);
                STEP256(R0, R1, Z0, Z1, k4*4+1, a0q.y, a1q.y);
                STEP256(R0, R1, Z0, Z1, k4*4+2, a0q.z, a1q.z);
                STEP256(R0, R1, Z0, Z1, k4*4+3, a0q.w, a1q.w);
            }
        }
        #pragma unroll
        for (int cc = 0; cc < 4; cc++) {
            float2 r0 = upk(R0[cc]); float2 r1 = upk(R1[cc]);
            float2 z0 = upk(Z0[cc]); float2 z1 = upk(Z1[cc]);
            rs[0][2*cc] = sigm(r0.x); rs[0][2*cc+1] = sigm(r0.y);
            rs[1][2*cc] = sigm(r1.x); rs[1][2*cc+1] = sigm(r1.y);
            zs[0][2*cc] = sigm(z0.x); zs[0][2*cc+1] = sigm(z0.y);
            zs[1][2*cc] = sigm(z1.x); zs[1][2*cc+1] = sigm(z1.y);
        }
    }

    // ======== GRU n : tiles g=16..19, KT=32 ========
    {
        u64t N0[4], N1[4], G0[4], G1[4];
        {
            float4 ni0 = *(const float4*)(gbi + 2*H + c0);
            float4 ni1 = *(const float4*)(gbi + 2*H + c0 + 4);
            float4 nh0 = *(const float4*)(gbh + 2*H + c0);
            float4 nh1 = *(const float4*)(gbh + 2*H + c0 + 4);
            N0[0] = pk2b(ni0.x, ni0.y); N0[1] = pk2b(ni0.z, ni0.w);
            N0[2] = pk2b(ni1.x, ni1.y); N0[3] = pk2b(ni1.z, ni1.w);
            G0[0] = pk2b(nh0.x, nh0.y); G0[1] = pk2b(nh0.z, nh0.w);
            G0[2] = pk2b(nh1.x, nh1.y); G0[3] = pk2b(nh1.z, nh1.w);
            #pragma unroll
            for (int i = 0; i < 4; i++) { N1[i] = N0[i]; G1[i] = G0[i]; }
        }
        #pragma unroll 1
        for (int t = 0; t < 4; t++) {
            int g = 16 + t;
            __syncthreads();
            STAGE_NEXT(g + 1);
            MB_WAIT(mbu + (g&1)*8, (g>>1)&1);
            const float* bw = sB + (g&1)*8192;
            const float4* x0v = (const float4*)(sC + rowA*SC_STR + t*32);
            const float4* x1v = x0v + (8*SC_STR)/4;
            const float4* h0v = x0v + 32;   // +128 floats
            const float4* h1v = x1v + 32;
            #pragma unroll
            for (int k4 = 0; k4 < 8; k4++) {
                float4 x0q = x0v[k4];
                float4 x1q = x1v[k4];
                float4 h0q = h0v[k4];
                float4 h1q = h1v[k4];
                STEPN(k4*4+0, x0q.x, x1q.x, h0q.x, h1q.x);
                STEPN(k4*4+1, x0q.y, x1q.y, h0q.y, h1q.y);
                STEPN(k4*4+2, x0q.z, x1q.z, h0q.z, h1q.z);
                STEPN(k4*4+3, x0q.w, x1q.w, h0q.w, h1q.w);
            }
        }

        // finalize h
        float hv0[8], hv1[8];
        const float* hp0 = sC + rowA*SC_STR + 128 + c0;
        const float* hp1 = hp0 + 8*SC_STR;
        #pragma unroll
        for (int cc = 0; cc < 4; cc++) {
            float2 nv0 = upk(N0[cc]); float2 gv0 = upk(G0[cc]);
            float2 nv1 = upk(N1[cc]); float2 gv1 = upk(G1[cc]);
            float n00 = tanhf(fmaf(rs[0][2*cc],   gv0.x, nv0.x));
            float n01 = tanhf(fmaf(rs[0][2*cc+1], gv0.y, nv0.y));
            float n10 = tanhf(fmaf(rs[1][2*cc],   gv1.x, nv1.x));
            float n11 = tanhf(fmaf(rs[1][2*cc+1], gv1.y, nv1.y));
            hv0[2*cc]   = (1.f - zs[0][2*cc])  * n00 + zs[0][2*cc]  * hp0[2*cc];
            hv0[2*cc+1] = (1.f - zs[0][2*cc+1])* n01 + zs[0][2*cc+1]* hp0[2*cc+1];
            hv1[2*cc]   = (1.f - zs[1][2*cc])  * n10 + zs[1][2*cc]  * hp1[2*cc];
            hv1[2*cc+1] = (1.f - zs[1][2*cc+1])* n11 + zs[1][2*cc+1]* hp1[2*cc+1];
        }
        int r0g = row0 + rowA, r1g = r0g + 8;
        *(float4*)&out[OFF_H + r0g*H + c0]     = make_float4(hv0[0], hv0[1], hv0[2], hv0[3]);
        *(float4*)&out[OFF_H + r0g*H + c0 + 4] = make_float4(hv0[4], hv0[5], hv0[6], hv0[7]);
        *(float4*)&out[OFF_H + r1g*H + c0]     = make_float4(hv1[0], hv1[1], hv1[2], hv1[3]);
        *(float4*)&out[OFF_H + r1g*H + c0 + 4] = make_float4(hv1[4], hv1[5], hv1[6], hv1[7]);

        __syncthreads();           // everyone done reading sC (x2/hp) + tile 19

        // write h into sC cols [0,128)
        float* ho0 = sC + rowA*SC_STR + c0;
        float* ho1 = ho0 + 8*SC_STR;
        #pragma unroll
        for (int cc = 0; cc < 8; cc++) { ho0[cc] = hv0[cc]; ho1[cc] = hv1[cc]; }
    }

    // ======== epilogue: qphi + fc2 + transpose + sort ========
    // sB: sQ [16][129] at 0 ; ssq [16][112] at 2176 ;
    //     sPhi [64][160 swz] at 4096 ; sCos [16][68] at 14336
    // sX: sW fc2_w padded [128][16]
    {
        float* sQ   = sB;
        float* ssq  = sB + 2176;
        float* sPhi = sB + 4096;      // stride 160, j' = j + 4*(j>>4)
        float* sCos = sB + 14336;     // stride 68
        float* sW   = sX;

        // cos table + rq out: thread (qq = tid>>3, fb = tid&7)
        {
            int qq = tid >> 3, fb = tid & 7;
            float rqv = __ldg(rq_in + row0 + qq);
            if (fb == 0) out[OFF_RQ + row0 + qq] = rqv;
            #pragma unroll
            for (int u = 0; u < 8; u++) {
                int f = fb*8 + u;
                sCos[qq*68 + f] = cospif((float)f * rqv);
            }
        }
        // stage phi_w swizzled + fc2_w padded
        #pragma unroll
        for (int i = tid; i < 2048; i += 128) {
            float4 v = ((const float4*)phi_w)[i];
            int f = i >> 5, jt = (i & 31)*4;
            float* p = sPhi + f*160 + jt + ((jt >> 4) << 2);
            p[0] = v.x; p[1] = v.y; p[2] = v.z; p[3] = v.w;
        }
        for (int i = tid; i < H*NA; i += 128) {
            int j = i / NA, na = i - j*NA;
            sW[j*16 + na] = fc2_w[i];
        }
        __syncthreads();

        // qphi: thread (qq = tid>>3, j0 = (tid&7)*16) -> 16 outputs
        {
            int qq = tid >> 3, fb = tid & 7;
            int j0 = fb * 16;
            const float* ph = sPhi + j0 + 4*fb;    // swizzled column base
            u64t acc[8];
            #pragma unroll
            for (int p = 0; p < 8; p++)
                acc[p] = pk2b(phi_b[j0 + 2*p], phi_b[j0 + 2*p + 1]);
            const float* crow = sCos + qq*68;
            #pragma unroll 8
            for (int f = 0; f < QED; f++) {
                u64t c2 = pk2(crow[f]);
                const float* pr = ph + f*160;
                ulonglong2 w01 = *(const ulonglong2*)pr;
                ulonglong2 w23 = *(const ulonglong2*)(pr + 4);
                ulonglong2 w45 = *(const ulonglong2*)(pr + 8);
                ulonglong2 w67 = *(const ulonglong2*)(pr + 12);
                fma2(acc[0], c2, w01.x); fma2(acc[1], c2, w01.y);
                fma2(acc[2], c2, w23.x); fma2(acc[3], c2, w23.y);
                fma2(acc[4], c2, w45.x); fma2(acc[5], c2, w45.y);
                fma2(acc[6], c2, w67.x); fma2(acc[7], c2, w67.y);
            }
            float* qo = sQ + qq*129 + j0;
            #pragma unroll
            for (int p = 0; p < 8; p++) {
                float2 v = upk(acc[p]);
                qo[2*p]   = fmaxf(v.x, 0.f);
                qo[2*p+1] = fmaxf(v.y, 0.f);
            }
        }
        __syncthreads();

        // fc2: thread (row = tid&15, qi = tid>>4)
        {
            const int row = tid & 15;
            const int qi  = tid >> 4;
            const float* hrow = sC + row*SC_STR;
            const float* qrow = sQ + ((row >> 3)*8 + qi)*129;
            u64t acc[7];
            #pragma unroll
            for (int p = 0; p < 7; p++) acc[p] = pk2b(fc2_b[2*p], fc2_b[2*p+1]);
            #pragma unroll 4
            for (int j = 0; j < H; j++) {
                float hq = hrow[j] * qrow[j];
                u64t h2 = pk2(hq);
                const ulonglong2* wp = (const ulonglong2*)(sW + j*16);
                ulonglong2 w0 = wp[0], w1 = wp[1];
                u64t w2 = *(const u64t*)(sW + j*16 + 8);
                u64t w3 = *(const u64t*)(sW + j*16 + 10);
                u64t w4 = *(const u64t*)(sW + j*16 + 12);
                fma2(acc[0], h2, w0.x); fma2(acc[1], h2, w0.y);
                fma2(acc[2], h2, w1.x); fma2(acc[3], h2, w1.y);
                fma2(acc[4], h2, w2);   fma2(acc[5], h2, w3);
                fma2(acc[6], h2, w4);
            }
            #pragma unroll
            for (int p = 0; p < 7; p++) {
                float2 v = upk(acc[p]);
                ssq[row*112 + (2*p)*8   + qi] = v.x;
                ssq[row*112 + (2*p+1)*8 + qi] = v.y;
            }
        }
        __syncthreads();

        // sort: 224 (row,na) pairs
        for (int p = tid; p < ROWS*NA; p += 128) {
            int r = p / NA, na = p - r*NA;
            const float* s = ssq + r*112 + na*8;
            float v[NQ];
            #pragma unroll
            for (int k = 0; k < NQ; k++) v[k] = s[k];
            #pragma unroll
            for (int i = 1; i < NQ; i++) {
                float key = v[i];
                int q = i - 1;
                while (q >= 0 && v[q] > key) { v[q+1] = v[q]; q--; }
                v[q+1] = key;
            }
            float* o = out + OFF_SQ + (row0 + r)*112 + na*8;
            *(float4*)o       = make_float4(v[0], v[1], v[2], v[3]);
            *(float4*)(o + 4) = make_float4(v[4], v[5], v[6], v[7]);
        }
    }
}

// ---------------------------------------------------------------------------
extern "C" void kernel_launch(void* const* d_in, const int* in_sizes, int n_in,
                              void* d_out, int out_size) {
    const float* in        = (const float*)d_in[0];
    const float* hidden    = (const float*)d_in[1];
    const float* rqs       = (const float*)d_in[2];
    const float* fc1_w     = (const float*)d_in[3];
    const float* fc1_b     = (const float*)d_in[4];
    const float* hyp_w1    = (const float*)d_in[5];
    const float* hyp_b1    = (const float*)d_in[6];
    const float* hyp_w2    = (const float*)d_in[7];
    const float* hyp_b2    = (const float*)d_in[8];
    const float* merger_w  = (const float*)d_in[9];
    const float* gru_wi    = (const float*)d_in[10];
    const float* gru_wh    = (const float*)d_in[11];
    const float* gru_bi    = (const float*)d_in[12];
    const float* gru_bh    = (const float*)d_in[13];
    const float* phi_w     = (const float*)d_in[14];
    const float* phi_b     = (const float*)d_in[15];
    const float* fc2_w     = (const float*)d_in[16];
    const float* fc2_b     = (const float*)d_in[17];
    float* out = (float*)d_out;

    static int smem_set = 0;
    if (!smem_set) {
        cudaFuncSetAttribute(k_main, cudaFuncAttributeMaxDynamicSharedMemorySize,
                             SMEM_BYTES);
        smem_set = 1;
    }

    k_main<<<BS/ROWS, 128, SMEM_BYTES>>>(in, hidden, fc1_w, fc1_b,
                                         hyp_w1, hyp_b1, hyp_w2, hyp_b2,
                                         merger_w, gru_wi, gru_wh,
                                         gru_bi, gru_bh,
                                         rqs, phi_w, phi_b, fc2_w, fc2_b, out);
}